// round 6
// baseline (speedup 1.0000x reference)
#include <cuda_runtime.h>
#include <cuda_bf16.h>
#include <cstdint>

typedef __nv_bfloat16 bf16;

#define H_ 1024
#define V_ 32000
#define B_ 16
#define T_ 256
#define R_ 4096   // B_*T_
#define NB 128    // persistent recurrence blocks

// ---------------- static device scratch (allocations are forbidden) ----------------
__device__ bf16  g_Xhi[R_ * H_];
__device__ bf16  g_Xlo[R_ * H_];
__device__ bf16  g_WcatT_hi[4 * H_ * H_];   // [n4][k]
__device__ bf16  g_WcatT_lo[4 * H_ * H_];
__device__ float g_bcat[4 * H_];
__device__ float g_XG[(size_t)R_ * 4 * H_]; // precomputed x-gate contributions (+bias)
__device__ float g_Upack[NB * H_ * 32];     // U repacked for recurrence
__device__ float g_Hbuf[H_ * 16];           // h, layout [n][b]
__device__ bf16  g_HShi[R_ * H_];
__device__ bf16  g_HSlo[R_ * H_];
__device__ bf16  g_WoutT_hi[32768000];      // V_*H_, layout [n][k]
__device__ bf16  g_WoutT_lo[32768000];
__device__ unsigned g_ctr[256];             // per-step grid-barrier counters

// ---------------- prep kernels ----------------
__global__ void zero_ctr_kernel() {
    if (threadIdx.x < 256) g_ctr[threadIdx.x] = 0u;
}

__global__ void bcat_kernel(const float* __restrict__ bf_, const float* __restrict__ bi_,
                            const float* __restrict__ bc_, const float* __restrict__ bo_) {
    int i = blockIdx.x * blockDim.x + threadIdx.x;
    if (i < 4 * H_) {
        int g = i >> 10, n = i & (H_ - 1);
        const float* b = (g == 0) ? bf_ : (g == 1) ? bi_ : (g == 2) ? bc_ : bo_;
        g_bcat[i] = b[n];
    }
}

__global__ void gather_split_kernel(const int* __restrict__ tokens,
                                    const float* __restrict__ emb) {
    for (int idx = blockIdx.x * blockDim.x + threadIdx.x; idx < R_ * H_;
         idx += gridDim.x * blockDim.x) {
        int r = idx >> 10, k = idx & (H_ - 1);
        float v = emb[(size_t)tokens[r] * H_ + k];
        bf16 h = __float2bfloat16(v);
        g_Xhi[idx] = h;
        g_Xlo[idx] = __float2bfloat16(v - __bfloat162float(h));
    }
}

// WcatT[n4][k] = w_g[k][n]  (n4 = g*1024 + n)  -- small (16MB), leave simple
__global__ void wcatT_split_kernel(const float* __restrict__ wf, const float* __restrict__ wi,
                                   const float* __restrict__ wc, const float* __restrict__ wo) {
    for (int idx = blockIdx.x * blockDim.x + threadIdx.x; idx < 4 * H_ * H_;
         idx += gridDim.x * blockDim.x) {
        int k = idx & 1023;
        int n4 = idx >> 10;
        int g = n4 >> 10, n = n4 & 1023;
        const float* w = (g == 0) ? wf : (g == 1) ? wi : (g == 2) ? wc : wo;
        float v = w[(size_t)k * H_ + n];
        bf16 h = __float2bfloat16(v);
        g_WcatT_hi[idx] = h;
        g_WcatT_lo[idx] = __float2bfloat16(v - __bfloat162float(h));
    }
}

// Tiled transpose+split: WoutT[n][k] = w_out[k][n], both sides coalesced.
__global__ __launch_bounds__(256) void woutT_split_kernel(const float* __restrict__ wout) {
    __shared__ float t[32][33];
    int n0 = blockIdx.x * 32, k0 = blockIdx.y * 32;
    int tx = threadIdx.x, ty = threadIdx.y;  // 32 x 8
#pragma unroll
    for (int i = ty; i < 32; i += 8) t[i][tx] = wout[(size_t)(k0 + i) * V_ + n0 + tx];
    __syncthreads();
#pragma unroll
    for (int i = ty; i < 32; i += 8) {
        float v = t[tx][i];
        bf16 h = __float2bfloat16(v);
        size_t o = (size_t)(n0 + i) * H_ + k0 + tx;
        g_WoutT_hi[o] = h;
        g_WoutT_lo[o] = __float2bfloat16(v - __bfloat162float(h));
    }
}

// Upack[(i*1024 + k)*32 + l] = u_g[k][8*i + j], where g = l>>3, j = l&7
__global__ void pack_u_kernel(const float* __restrict__ uf, const float* __restrict__ ui,
                              const float* __restrict__ uc, const float* __restrict__ uo) {
    for (int idx = blockIdx.x * blockDim.x + threadIdx.x; idx < NB * H_ * 32;
         idx += gridDim.x * blockDim.x) {
        int l = idx & 31;
        int k = (idx >> 5) & 1023;
        int i = idx >> 15;
        int g = l >> 3, j = l & 7;
        const float* u = (g == 0) ? uf : (g == 1) ? ui : (g == 2) ? uc : uo;
        g_Upack[idx] = u[(size_t)k * H_ + 8 * i + j];
    }
}

// ---------------- split-bf16 GEMM: C[M,N] = A[M,K] * B^T[N,K] + bias ----------------
// A [M][K] (hi/lo), Bt [N][K] (hi/lo). 128x128 tiles, BK=32, cp.async 2-stage pipeline,
// ldmatrix fragments. C = Ah*Bh + Ah*Bl + Al*Bh (fp32 accum).

__device__ __forceinline__ void mma16816(float c[4], const uint32_t a[4], uint32_t b0,
                                         uint32_t b1) {
    asm volatile(
        "mma.sync.aligned.m16n8k16.row.col.f32.bf16.bf16.f32 "
        "{%0,%1,%2,%3}, {%4,%5,%6,%7}, {%8,%9}, {%0,%1,%2,%3};\n"
        : "+f"(c[0]), "+f"(c[1]), "+f"(c[2]), "+f"(c[3])
        : "r"(a[0]), "r"(a[1]), "r"(a[2]), "r"(a[3]), "r"(b0), "r"(b1));
}

__device__ __forceinline__ void cp16(bf16* dst, const bf16* src) {
    uint32_t d = (uint32_t)__cvta_generic_to_shared(dst);
    asm volatile("cp.async.cg.shared.global [%0], [%1], 16;" ::"r"(d), "l"(src));
}

__device__ __forceinline__ void ldm_x4(uint32_t r[4], const bf16* p) {
    uint32_t a = (uint32_t)__cvta_generic_to_shared(p);
    asm volatile("ldmatrix.sync.aligned.m8n8.x4.shared.b16 {%0,%1,%2,%3}, [%4];"
                 : "=r"(r[0]), "=r"(r[1]), "=r"(r[2]), "=r"(r[3])
                 : "r"(a));
}

#define SROW 40  // padded smem row (bf16 elems): 80B, 16B-aligned, bank-conflict-free

__global__ __launch_bounds__(256) void gemm_split_kernel(
    const bf16* __restrict__ Ahi, const bf16* __restrict__ Alo, const bf16* __restrict__ Bhi,
    const bf16* __restrict__ Blo, const float* __restrict__ bias, float* __restrict__ C, int M,
    int N, int K) {
    extern __shared__ bf16 gsm[];
    // layout: A[stage][h][128][SROW] then B[stage][h][128][SROW]
    bf16* sA[2][2];
    bf16* sB[2][2];
#pragma unroll
    for (int s = 0; s < 2; s++)
#pragma unroll
        for (int h = 0; h < 2; h++) {
            sA[s][h] = gsm + (size_t)(s * 2 + h) * 128 * SROW;
            sB[s][h] = gsm + (size_t)4 * 128 * SROW + (size_t)(s * 2 + h) * 128 * SROW;
        }

    const int tid = threadIdx.x;
    const int lane = tid & 31, warp = tid >> 5;
    const int wm = warp & 3, wn = warp >> 2;

    // L2 swizzle: panels of 4 m-tiles sweep all n-tiles
    const int nt = N >> 7;
    int bid = blockIdx.x;
    int panel = bid / (4 * nt);
    int ii = bid - panel * 4 * nt;
    const int bm0 = (panel * 4 + (ii & 3)) << 7;
    const int bn0 = (ii >> 2) << 7;

    float acc[2][8][4];
#pragma unroll
    for (int mi = 0; mi < 2; mi++)
#pragma unroll
        for (int nj = 0; nj < 8; nj++)
#pragma unroll
            for (int e = 0; e < 4; e++) acc[mi][nj][e] = 0.f;

    auto issue = [&](int s, int k0) {
#pragma unroll
        for (int q = 0; q < 2; q++) {
            int idx = q * 256 + tid;
            int r = idx >> 2, c = idx & 3;
            int off = r * SROW + c * 8;
            cp16(sA[s][0] + off, Ahi + (size_t)(bm0 + r) * K + k0 + c * 8);
            cp16(sA[s][1] + off, Alo + (size_t)(bm0 + r) * K + k0 + c * 8);
            cp16(sB[s][0] + off, Bhi + (size_t)(bn0 + r) * K + k0 + c * 8);
            cp16(sB[s][1] + off, Blo + (size_t)(bn0 + r) * K + k0 + c * 8);
        }
        asm volatile("cp.async.commit_group;");
    };

    issue(0, 0);
    const int nk = K >> 5;

    for (int kt = 0; kt < nk; kt++) {
        asm volatile("cp.async.wait_group 0;");
        __syncthreads();
        if (kt + 1 < nk) issue((kt + 1) & 1, (kt + 1) << 5);
        const int s = kt & 1;

#pragma unroll
        for (int ks = 0; ks < 32; ks += 16) {
            uint32_t a[2][2][4];
            const int arow = wm * 32 + (lane & 15);
            const int acol = ks + ((lane >> 4) << 3);
#pragma unroll
            for (int h = 0; h < 2; h++)
#pragma unroll
                for (int mi = 0; mi < 2; mi++)
                    ldm_x4(a[h][mi], sA[s][h] + (arow + mi * 16) * SROW + acol);

            uint32_t b[2][8][2];
            const int tq = lane >> 3;
            const int brow = ((tq >> 1) << 3) + (lane & 7);
            const int bcol = ks + ((tq & 1) << 3);
#pragma unroll
            for (int h = 0; h < 2; h++)
#pragma unroll
                for (int pj = 0; pj < 4; pj++) {
                    uint32_t r4[4];
                    ldm_x4(r4, sB[s][h] + (wn * 64 + pj * 16 + brow) * SROW + bcol);
                    b[h][2 * pj][0] = r4[0];
                    b[h][2 * pj][1] = r4[1];
                    b[h][2 * pj + 1][0] = r4[2];
                    b[h][2 * pj + 1][1] = r4[3];
                }

#pragma unroll
            for (int nj = 0; nj < 8; nj++)
#pragma unroll
                for (int mi = 0; mi < 2; mi++) {
                    mma16816(acc[mi][nj], a[0][mi], b[0][nj][0], b[0][nj][1]);
                    mma16816(acc[mi][nj], a[0][mi], b[1][nj][0], b[1][nj][1]);
                    mma16816(acc[mi][nj], a[1][mi], b[0][nj][0], b[0][nj][1]);
                }
        }
        __syncthreads();
    }

    const int g = lane >> 2, tg = lane & 3;
#pragma unroll
    for (int mi = 0; mi < 2; mi++) {
#pragma unroll
        for (int nj = 0; nj < 8; nj++) {
            int r = bm0 + wm * 32 + mi * 16 + g;
            int nc = bn0 + wn * 64 + nj * 8 + 2 * tg;
            float b0 = bias[nc], b1 = bias[nc + 1];
            float2 v0 = make_float2(acc[mi][nj][0] + b0, acc[mi][nj][1] + b1);
            float2 v1 = make_float2(acc[mi][nj][2] + b0, acc[mi][nj][3] + b1);
            *(float2*)&C[(size_t)r * N + nc] = v0;
            *(float2*)&C[(size_t)(r + 8) * N + nc] = v1;
        }
    }
}

// ---------------- persistent LSTM recurrence ----------------
// 128 blocks x 256 threads, block i owns h-cols [8i, 8i+8).
extern __shared__ float recur_smem[];

__global__ __launch_bounds__(256) void recur_kernel() {
    float* hsm = recur_smem;        // 16384 floats, layout [k][16]
    float* Gs = hsm + 16384;        // 512:  [g][r][j]
    float* red = Gs + 512;          // 512:  kh=1 partials
    float* csm = red + 512;         // 128:  cell state

    const int i = blockIdx.x;
    const int tid = threadIdx.x;
    const int l = tid & 31;
    const int rg = (tid >> 5) & 3;
    const int kh = tid >> 7;
    const int gg = l >> 3, jj = l & 7;

    if (tid < 128) csm[tid] = 0.f;
    const float* up_base = g_Upack + ((size_t)i * 1024 + kh * 512) * 32 + l;

    for (int t = 0; t < 256; t++) {
        float a0 = 0.f, a1 = 0.f, a2 = 0.f, a3 = 0.f;
        if (t > 0) {
            const float4* src = (const float4*)g_Hbuf;
            float4* dst = (float4*)hsm;
#pragma unroll
            for (int q = 0; q < 16; q++) dst[tid + q * 256] = src[tid + q * 256];
            __syncthreads();
            const float* up = up_base;
            const float4* hp = (const float4*)(hsm + kh * 512 * 16 + rg * 4);
#pragma unroll 8
            for (int k = 0; k < 512; k++) {
                float u = up[k * 32];
                float4 hv = hp[k * 4];
                a0 += hv.x * u;
                a1 += hv.y * u;
                a2 += hv.z * u;
                a3 += hv.w * u;
            }
        }
        if (kh == 1) {
            red[(tid - 128) * 4 + 0] = a0;
            red[(tid - 128) * 4 + 1] = a1;
            red[(tid - 128) * 4 + 2] = a2;
            red[(tid - 128) * 4 + 3] = a3;
        }
        __syncthreads();
        if (kh == 0) {
            a0 += red[tid * 4 + 0];
            a1 += red[tid * 4 + 1];
            a2 += red[tid * 4 + 2];
            a3 += red[tid * 4 + 3];
            float* gp = Gs + gg * 128 + jj;
            gp[(4 * rg + 0) * 8] = a0;
            gp[(4 * rg + 1) * 8] = a1;
            gp[(4 * rg + 2) * 8] = a2;
            gp[(4 * rg + 3) * 8] = a3;
        }
        __syncthreads();
        if (tid < 128) {
            int r = tid >> 3, j = tid & 7;
            int n = 8 * i + j;
            int row = r * 256 + t;
            const float* xg = g_XG + (size_t)row * 4096 + n;
            float pf = Gs[0 * 128 + r * 8 + j] + xg[0];
            float pi = Gs[1 * 128 + r * 8 + j] + xg[1024];
            float pc = Gs[2 * 128 + r * 8 + j] + xg[2048];
            float po = Gs[3 * 128 + r * 8 + j] + xg[3072];
            float f = 1.f / (1.f + expf(-pf));
            float ig = 1.f / (1.f + expf(-pi));
            float cd = tanhf(pc);
            float o = 1.f / (1.f + expf(-po));
            float c = f * csm[tid] + ig * cd;
            csm[tid] = c;
            float h = o * tanhf(c);
            g_Hbuf[n * 16 + r] = h;
            size_t hidx = (size_t)row * 1024 + n;
            bf16 hh = __float2bfloat16(h);
            g_HShi[hidx] = hh;
            g_HSlo[hidx] = __float2bfloat16(h - __bfloat162float(hh));
        }
        if (t < 255) {
            __threadfence();
            __syncthreads();
            if (tid == 0) {
                atomicAdd(&g_ctr[t], 1u);
                while (*((volatile unsigned*)&g_ctr[t]) < (unsigned)NB) {
                }
                __threadfence();
            }
            __syncthreads();
        }
    }
}

// ---------------- launch ----------------
extern "C" void kernel_launch(void* const* d_in, const int* in_sizes, int n_in, void* d_out,
                              int out_size) {
    const int* tokens = (const int*)d_in[0];
    const float* emb = (const float*)d_in[1];
    const float* w_f = (const float*)d_in[2];
    const float* u_f = (const float*)d_in[3];
    const float* b_f = (const float*)d_in[4];
    const float* w_i = (const float*)d_in[5];
    const float* u_i = (const float*)d_in[6];
    const float* b_i = (const float*)d_in[7];
    const float* w_c = (const float*)d_in[8];
    const float* u_c = (const float*)d_in[9];
    const float* b_c = (const float*)d_in[10];
    const float* w_o = (const float*)d_in[11];
    const float* u_o = (const float*)d_in[12];
    const float* b_o = (const float*)d_in[13];
    const float* w_out = (const float*)d_in[14];
    const float* b_out = (const float*)d_in[15];
    float* out = (float*)d_out;

    const int recur_smem_bytes = (16384 + 512 + 512 + 128) * 4;  // 70144
    cudaFuncSetAttribute(recur_kernel, cudaFuncAttributeMaxDynamicSharedMemorySize,
                         recur_smem_bytes);
    const int gemm_smem_bytes = 8 * 128 * SROW * 2;  // 81920
    cudaFuncSetAttribute(gemm_split_kernel, cudaFuncAttributeMaxDynamicSharedMemorySize,
                         gemm_smem_bytes);

    void *p_xhi, *p_xlo, *p_wch, *p_wcl, *p_bcat, *p_xg, *p_hshi, *p_hslo, *p_woh, *p_wol;
    cudaGetSymbolAddress(&p_xhi, g_Xhi);
    cudaGetSymbolAddress(&p_xlo, g_Xlo);
    cudaGetSymbolAddress(&p_wch, g_WcatT_hi);
    cudaGetSymbolAddress(&p_wcl, g_WcatT_lo);
    cudaGetSymbolAddress(&p_bcat, g_bcat);
    cudaGetSymbolAddress(&p_xg, g_XG);
    cudaGetSymbolAddress(&p_hshi, g_HShi);
    cudaGetSymbolAddress(&p_hslo, g_HSlo);
    cudaGetSymbolAddress(&p_woh, g_WoutT_hi);
    cudaGetSymbolAddress(&p_wol, g_WoutT_lo);

    zero_ctr_kernel<<<1, 256>>>();
    bcat_kernel<<<16, 256>>>(b_f, b_i, b_c, b_o);
    gather_split_kernel<<<4096, 256>>>(tokens, emb);
    wcatT_split_kernel<<<4096, 256>>>(w_f, w_i, w_c, w_o);
    pack_u_kernel<<<4096, 256>>>(u_f, u_i, u_c, u_o);
    woutT_split_kernel<<<dim3(V_ / 32, H_ / 32), dim3(32, 8)>>>(w_out);

    // XG = X @ Wcat + bcat   (M=4096, N=4096, K=1024)
    gemm_split_kernel<<<(R_ / 128) * (4 * H_ / 128), 256, gemm_smem_bytes>>>(
        (const bf16*)p_xhi, (const bf16*)p_xlo, (const bf16*)p_wch, (const bf16*)p_wcl,
        (const float*)p_bcat, (float*)p_xg, R_, 4 * H_, H_);

    // sequential LSTM recurrence (persistent, 1 grid barrier per step)
    recur_kernel<<<NB, 256, recur_smem_bytes>>>();

    // logits = HS @ w_out + b_out   (M=4096, N=32000, K=1024)
    gemm_split_kernel<<<(R_ / 128) * (V_ / 128), 256, gemm_smem_bytes>>>(
        (const bf16*)p_hshi, (const bf16*)p_hslo, (const bf16*)p_woh, (const bf16*)p_wol, b_out,
        out, R_, V_, H_);
}

// round 9
// speedup vs baseline: 1.3936x; 1.3936x over previous
#include <cuda_runtime.h>
#include <cuda_bf16.h>
#include <cstdint>

typedef __nv_bfloat16 bf16;

#define H_ 1024
#define V_ 32000
#define B_ 16
#define T_ 256
#define R_ 4096   // B_*T_
#define NB 128    // persistent recurrence blocks

// ---------------- static device scratch (allocations are forbidden) ----------------
__device__ bf16  g_Xhi[R_ * H_];
__device__ bf16  g_Xlo[R_ * H_];
__device__ bf16  g_WcatT_hi[4 * H_ * H_];   // [n4][k]
__device__ bf16  g_WcatT_lo[4 * H_ * H_];
__device__ float g_bcat[4 * H_];
__device__ float g_XG[(size_t)R_ * 4 * H_]; // precomputed x-gate contributions (+bias)
__device__ float g_Upack[NB * H_ * 32];     // U repacked for recurrence
__device__ float g_Hbuf[H_ * 16];           // h, layout [n][b]
__device__ bf16  g_HShi[R_ * H_];
__device__ bf16  g_HSlo[R_ * H_];
__device__ bf16  g_WoutT_hi[32768000];      // V_*H_, layout [n][k]
__device__ bf16  g_WoutT_lo[32768000];
__device__ unsigned g_ctr[256];             // per-step grid-barrier counters

// ---------------- prep kernels ----------------
__global__ void zero_ctr_kernel() {
    if (threadIdx.x < 256) g_ctr[threadIdx.x] = 0u;
}

__global__ void bcat_kernel(const float* __restrict__ bf_, const float* __restrict__ bi_,
                            const float* __restrict__ bc_, const float* __restrict__ bo_) {
    int i = blockIdx.x * blockDim.x + threadIdx.x;
    if (i < 4 * H_) {
        int g = i >> 10, n = i & (H_ - 1);
        const float* b = (g == 0) ? bf_ : (g == 1) ? bi_ : (g == 2) ? bc_ : bo_;
        g_bcat[i] = b[n];
    }
}

__global__ void gather_split_kernel(const int* __restrict__ tokens,
                                    const float* __restrict__ emb) {
    for (int idx = blockIdx.x * blockDim.x + threadIdx.x; idx < R_ * H_;
         idx += gridDim.x * blockDim.x) {
        int r = idx >> 10, k = idx & (H_ - 1);
        float v = emb[(size_t)tokens[r] * H_ + k];
        bf16 h = __float2bfloat16(v);
        g_Xhi[idx] = h;
        g_Xlo[idx] = __float2bfloat16(v - __bfloat162float(h));
    }
}

// WcatT[n4][k] = w_g[k][n]  (n4 = g*1024 + n)
__global__ void wcatT_split_kernel(const float* __restrict__ wf, const float* __restrict__ wi,
                                   const float* __restrict__ wc, const float* __restrict__ wo) {
    for (int idx = blockIdx.x * blockDim.x + threadIdx.x; idx < 4 * H_ * H_;
         idx += gridDim.x * blockDim.x) {
        int k = idx & 1023;
        int n4 = idx >> 10;
        int g = n4 >> 10, n = n4 & 1023;
        const float* w = (g == 0) ? wf : (g == 1) ? wi : (g == 2) ? wc : wo;
        float v = w[(size_t)k * H_ + n];
        bf16 h = __float2bfloat16(v);
        g_WcatT_hi[idx] = h;
        g_WcatT_lo[idx] = __float2bfloat16(v - __bfloat162float(h));
    }
}

// Tiled transpose+split: WoutT[n][k] = w_out[k][n], both sides coalesced.
__global__ __launch_bounds__(256) void woutT_split_kernel(const float* __restrict__ wout) {
    __shared__ float t[32][33];
    int n0 = blockIdx.x * 32, k0 = blockIdx.y * 32;
    int tx = threadIdx.x, ty = threadIdx.y;  // 32 x 8
#pragma unroll
    for (int i = ty; i < 32; i += 8) t[i][tx] = wout[(size_t)(k0 + i) * V_ + n0 + tx];
    __syncthreads();
#pragma unroll
    for (int i = ty; i < 32; i += 8) {
        float v = t[tx][i];
        bf16 h = __float2bfloat16(v);
        size_t o = (size_t)(n0 + i) * H_ + k0 + tx;
        g_WoutT_hi[o] = h;
        g_WoutT_lo[o] = __float2bfloat16(v - __bfloat162float(h));
    }
}

// Upack[(i*1024 + k)*32 + l] = u_g[k][8*i + j], where g = l>>3, j = l&7
__global__ void pack_u_kernel(const float* __restrict__ uf, const float* __restrict__ ui,
                              const float* __restrict__ uc, const float* __restrict__ uo) {
    for (int idx = blockIdx.x * blockDim.x + threadIdx.x; idx < NB * H_ * 32;
         idx += gridDim.x * blockDim.x) {
        int l = idx & 31;
        int k = (idx >> 5) & 1023;
        int i = idx >> 15;
        int g = l >> 3, j = l & 7;
        const float* u = (g == 0) ? uf : (g == 1) ? ui : (g == 2) ? uc : uo;
        g_Upack[idx] = u[(size_t)k * H_ + 8 * i + j];
    }
}

// ---------------- split-bf16 GEMM: C[M,N] = A[M,K] * B^T[N,K] + bias ----------------
// A [M][K] (hi/lo), Bt [N][K] (hi/lo). 128x128 tiles, BK=32.
// cp.async 2-stage smem pipeline; proven scalar-LDS compute inner loop (round-3).
// C = Ah*Bh + Ah*Bl + Al*Bh (fp32 accum), rel err ~1e-5.

__device__ __forceinline__ void mma16816(float c[4], const uint32_t a[4], uint32_t b0,
                                         uint32_t b1) {
    asm volatile(
        "mma.sync.aligned.m16n8k16.row.col.f32.bf16.bf16.f32 "
        "{%0,%1,%2,%3}, {%4,%5,%6,%7}, {%8,%9}, {%0,%1,%2,%3};\n"
        : "+f"(c[0]), "+f"(c[1]), "+f"(c[2]), "+f"(c[3])
        : "r"(a[0]), "r"(a[1]), "r"(a[2]), "r"(a[3]), "r"(b0), "r"(b1));
}

__device__ __forceinline__ void cp16(bf16* dst, const bf16* src) {
    uint32_t d = (uint32_t)__cvta_generic_to_shared(dst);
    asm volatile("cp.async.cg.shared.global [%0], [%1], 16;" ::"r"(d), "l"(src));
}

#define SROW 40  // padded smem row (bf16 elems): 80B, conflict-free for LDS pattern

__global__ __launch_bounds__(256) void gemm_split_kernel(
    const bf16* __restrict__ Ahi, const bf16* __restrict__ Alo, const bf16* __restrict__ Bhi,
    const bf16* __restrict__ Blo, const float* __restrict__ bias, float* __restrict__ C, int M,
    int N, int K) {
    extern __shared__ bf16 gsm[];
    // layout: A[stage][h][128][SROW] then B[stage][h][128][SROW]
    bf16* sA[2][2];
    bf16* sB[2][2];
#pragma unroll
    for (int s = 0; s < 2; s++)
#pragma unroll
        for (int h = 0; h < 2; h++) {
            sA[s][h] = gsm + (size_t)(s * 2 + h) * 128 * SROW;
            sB[s][h] = gsm + (size_t)4 * 128 * SROW + (size_t)(s * 2 + h) * 128 * SROW;
        }

    const int tid = threadIdx.x;
    const int lane = tid & 31, warp = tid >> 5;
    const int wm = warp & 3, wn = warp >> 2;
    const int g = lane >> 2, tg = lane & 3;

    // L2 swizzle: panels of 4 m-tiles sweep all n-tiles
    const int nt = N >> 7;
    int bid = blockIdx.x;
    int panel = bid / (4 * nt);
    int ii = bid - panel * 4 * nt;
    const int bm0 = (panel * 4 + (ii & 3)) << 7;
    const int bn0 = (ii >> 2) << 7;

    float acc[2][8][4];
#pragma unroll
    for (int mi = 0; mi < 2; mi++)
#pragma unroll
        for (int nj = 0; nj < 8; nj++)
#pragma unroll
            for (int e = 0; e < 4; e++) acc[mi][nj][e] = 0.f;

    auto issue = [&](int s, int k0) {
#pragma unroll
        for (int q = 0; q < 2; q++) {
            int idx = q * 256 + tid;
            int r = idx >> 2, c = idx & 3;
            int off = r * SROW + c * 8;
            cp16(sA[s][0] + off, Ahi + (size_t)(bm0 + r) * K + k0 + c * 8);
            cp16(sA[s][1] + off, Alo + (size_t)(bm0 + r) * K + k0 + c * 8);
            cp16(sB[s][0] + off, Bhi + (size_t)(bn0 + r) * K + k0 + c * 8);
            cp16(sB[s][1] + off, Blo + (size_t)(bn0 + r) * K + k0 + c * 8);
        }
        asm volatile("cp.async.commit_group;");
    };

    issue(0, 0);
    const int nk = K >> 5;

    for (int kt = 0; kt < nk; kt++) {
        asm volatile("cp.async.wait_group 0;");
        __syncthreads();
        if (kt + 1 < nk) issue((kt + 1) & 1, (kt + 1) << 5);
        const int s = kt & 1;
        const bf16* As0 = sA[s][0];
        const bf16* As1 = sA[s][1];
        const bf16* Bs0 = sB[s][0];
        const bf16* Bs1 = sB[s][1];

#pragma unroll
        for (int ks = 0; ks < 32; ks += 16) {
            uint32_t ah[2][4], al[2][4];
#pragma unroll
            for (int mi = 0; mi < 2; mi++) {
                int r0 = wm * 32 + mi * 16 + g;
                ah[mi][0] = *(const uint32_t*)&As0[r0 * SROW + ks + 2 * tg];
                ah[mi][1] = *(const uint32_t*)&As0[(r0 + 8) * SROW + ks + 2 * tg];
                ah[mi][2] = *(const uint32_t*)&As0[r0 * SROW + ks + 2 * tg + 8];
                ah[mi][3] = *(const uint32_t*)&As0[(r0 + 8) * SROW + ks + 2 * tg + 8];
                al[mi][0] = *(const uint32_t*)&As1[r0 * SROW + ks + 2 * tg];
                al[mi][1] = *(const uint32_t*)&As1[(r0 + 8) * SROW + ks + 2 * tg];
                al[mi][2] = *(const uint32_t*)&As1[r0 * SROW + ks + 2 * tg + 8];
                al[mi][3] = *(const uint32_t*)&As1[(r0 + 8) * SROW + ks + 2 * tg + 8];
            }
#pragma unroll
            for (int nj = 0; nj < 8; nj++) {
                int n = wn * 64 + nj * 8 + g;
                uint32_t bh0 = *(const uint32_t*)&Bs0[n * SROW + ks + 2 * tg];
                uint32_t bh1 = *(const uint32_t*)&Bs0[n * SROW + ks + 2 * tg + 8];
                uint32_t bl0 = *(const uint32_t*)&Bs1[n * SROW + ks + 2 * tg];
                uint32_t bl1 = *(const uint32_t*)&Bs1[n * SROW + ks + 2 * tg + 8];
#pragma unroll
                for (int mi = 0; mi < 2; mi++) {
                    mma16816(acc[mi][nj], ah[mi], bh0, bh1);
                    mma16816(acc[mi][nj], ah[mi], bl0, bl1);
                    mma16816(acc[mi][nj], al[mi], bh0, bh1);
                }
            }
        }
        __syncthreads();
    }

#pragma unroll
    for (int mi = 0; mi < 2; mi++) {
#pragma unroll
        for (int nj = 0; nj < 8; nj++) {
            int r = bm0 + wm * 32 + mi * 16 + g;
            int nc = bn0 + wn * 64 + nj * 8 + 2 * tg;
            float b0 = bias[nc], b1 = bias[nc + 1];
            float2 v0 = make_float2(acc[mi][nj][0] + b0, acc[mi][nj][1] + b1);
            float2 v1 = make_float2(acc[mi][nj][2] + b0, acc[mi][nj][3] + b1);
            *(float2*)&C[(size_t)r * N + nc] = v0;
            *(float2*)&C[(size_t)(r + 8) * N + nc] = v1;
        }
    }
}

// ---------------- persistent LSTM recurrence ----------------
// 128 blocks x 256 threads, block i owns h-cols [8i, 8i+8).
extern __shared__ float recur_smem[];

__global__ __launch_bounds__(256) void recur_kernel() {
    float* hsm = recur_smem;        // 16384 floats, layout [k][16]
    float* Gs = hsm + 16384;        // 512:  [g][r][j]
    float* red = Gs + 512;          // 512:  kh=1 partials
    float* csm = red + 512;         // 128:  cell state

    const int i = blockIdx.x;
    const int tid = threadIdx.x;
    const int l = tid & 31;
    const int rg = (tid >> 5) & 3;
    const int kh = tid >> 7;
    const int gg = l >> 3, jj = l & 7;

    if (tid < 128) csm[tid] = 0.f;
    const float* up_base = g_Upack + ((size_t)i * 1024 + kh * 512) * 32 + l;

    for (int t = 0; t < 256; t++) {
        float a0 = 0.f, a1 = 0.f, a2 = 0.f, a3 = 0.f;
        if (t > 0) {
            const float4* src = (const float4*)g_Hbuf;
            float4* dst = (float4*)hsm;
#pragma unroll
            for (int q = 0; q < 16; q++) dst[tid + q * 256] = src[tid + q * 256];
            __syncthreads();
            const float* up = up_base;
            const float4* hp = (const float4*)(hsm + kh * 512 * 16 + rg * 4);
#pragma unroll 8
            for (int k = 0; k < 512; k++) {
                float u = up[k * 32];
                float4 hv = hp[k * 4];
                a0 += hv.x * u;
                a1 += hv.y * u;
                a2 += hv.z * u;
                a3 += hv.w * u;
            }
        }
        if (kh == 1) {
            red[(tid - 128) * 4 + 0] = a0;
            red[(tid - 128) * 4 + 1] = a1;
            red[(tid - 128) * 4 + 2] = a2;
            red[(tid - 128) * 4 + 3] = a3;
        }
        __syncthreads();
        if (kh == 0) {
            a0 += red[tid * 4 + 0];
            a1 += red[tid * 4 + 1];
            a2 += red[tid * 4 + 2];
            a3 += red[tid * 4 + 3];
            float* gp = Gs + gg * 128 + jj;
            gp[(4 * rg + 0) * 8] = a0;
            gp[(4 * rg + 1) * 8] = a1;
            gp[(4 * rg + 2) * 8] = a2;
            gp[(4 * rg + 3) * 8] = a3;
        }
        __syncthreads();
        if (tid < 128) {
            int r = tid >> 3, j = tid & 7;
            int n = 8 * i + j;
            int row = r * 256 + t;
            const float* xg = g_XG + (size_t)row * 4096 + n;
            float pf = Gs[0 * 128 + r * 8 + j] + xg[0];
            float pi = Gs[1 * 128 + r * 8 + j] + xg[1024];
            float pc = Gs[2 * 128 + r * 8 + j] + xg[2048];
            float po = Gs[3 * 128 + r * 8 + j] + xg[3072];
            float f = 1.f / (1.f + expf(-pf));
            float ig = 1.f / (1.f + expf(-pi));
            float cd = tanhf(pc);
            float o = 1.f / (1.f + expf(-po));
            float c = f * csm[tid] + ig * cd;
            csm[tid] = c;
            float h = o * tanhf(c);
            g_Hbuf[n * 16 + r] = h;
            size_t hidx = (size_t)row * 1024 + n;
            bf16 hh = __float2bfloat16(h);
            g_HShi[hidx] = hh;
            g_HSlo[hidx] = __float2bfloat16(h - __bfloat162float(hh));
        }
        if (t < 255) {
            __threadfence();
            __syncthreads();
            if (tid == 0) {
                atomicAdd(&g_ctr[t], 1u);
                while (*((volatile unsigned*)&g_ctr[t]) < (unsigned)NB) {
                }
                __threadfence();
            }
            __syncthreads();
        }
    }
}

// ---------------- launch ----------------
extern "C" void kernel_launch(void* const* d_in, const int* in_sizes, int n_in, void* d_out,
                              int out_size) {
    const int* tokens = (const int*)d_in[0];
    const float* emb = (const float*)d_in[1];
    const float* w_f = (const float*)d_in[2];
    const float* u_f = (const float*)d_in[3];
    const float* b_f = (const float*)d_in[4];
    const float* w_i = (const float*)d_in[5];
    const float* u_i = (const float*)d_in[6];
    const float* b_i = (const float*)d_in[7];
    const float* w_c = (const float*)d_in[8];
    const float* u_c = (const float*)d_in[9];
    const float* b_c = (const float*)d_in[10];
    const float* w_o = (const float*)d_in[11];
    const float* u_o = (const float*)d_in[12];
    const float* b_o = (const float*)d_in[13];
    const float* w_out = (const float*)d_in[14];
    const float* b_out = (const float*)d_in[15];
    float* out = (float*)d_out;

    const int recur_smem_bytes = (16384 + 512 + 512 + 128) * 4;  // 70144
    cudaFuncSetAttribute(recur_kernel, cudaFuncAttributeMaxDynamicSharedMemorySize,
                         recur_smem_bytes);
    const int gemm_smem_bytes = 8 * 128 * SROW * 2;  // 81920
    cudaFuncSetAttribute(gemm_split_kernel, cudaFuncAttributeMaxDynamicSharedMemorySize,
                         gemm_smem_bytes);

    void *p_xhi, *p_xlo, *p_wch, *p_wcl, *p_bcat, *p_xg, *p_hshi, *p_hslo, *p_woh, *p_wol;
    cudaGetSymbolAddress(&p_xhi, g_Xhi);
    cudaGetSymbolAddress(&p_xlo, g_Xlo);
    cudaGetSymbolAddress(&p_wch, g_WcatT_hi);
    cudaGetSymbolAddress(&p_wcl, g_WcatT_lo);
    cudaGetSymbolAddress(&p_bcat, g_bcat);
    cudaGetSymbolAddress(&p_xg, g_XG);
    cudaGetSymbolAddress(&p_hshi, g_HShi);
    cudaGetSymbolAddress(&p_hslo, g_HSlo);
    cudaGetSymbolAddress(&p_woh, g_WoutT_hi);
    cudaGetSymbolAddress(&p_wol, g_WoutT_lo);

    zero_ctr_kernel<<<1, 256>>>();
    bcat_kernel<<<16, 256>>>(b_f, b_i, b_c, b_o);
    gather_split_kernel<<<4096, 256>>>(tokens, emb);
    wcatT_split_kernel<<<4096, 256>>>(w_f, w_i, w_c, w_o);
    pack_u_kernel<<<4096, 256>>>(u_f, u_i, u_c, u_o);
    woutT_split_kernel<<<dim3(V_ / 32, H_ / 32), dim3(32, 8)>>>(w_out);

    // XG = X @ Wcat + bcat   (M=4096, N=4096, K=1024)
    gemm_split_kernel<<<(R_ / 128) * (4 * H_ / 128), 256, gemm_smem_bytes>>>(
        (const bf16*)p_xhi, (const bf16*)p_xlo, (const bf16*)p_wch, (const bf16*)p_wcl,
        (const float*)p_bcat, (float*)p_xg, R_, 4 * H_, H_);

    // sequential LSTM recurrence (persistent, 1 grid barrier per step)
    recur_kernel<<<NB, 256, recur_smem_bytes>>>();

    // logits = HS @ w_out + b_out   (M=4096, N=32000, K=1024)
    gemm_split_kernel<<<(R_ / 128) * (V_ / 128), 256, gemm_smem_bytes>>>(
        (const bf16*)p_hshi, (const bf16*)p_hslo, (const bf16*)p_woh, (const bf16*)p_wol, b_out,
        out, R_, V_, H_);
}

// round 10
// speedup vs baseline: 1.4085x; 1.0107x over previous
#include <cuda_runtime.h>
#include <cuda_bf16.h>
#include <cstdint>

typedef __nv_bfloat16 bf16;

#define H_ 1024
#define V_ 32000
#define B_ 16
#define T_ 256
#define R_ 4096   // B_*T_
#define NB 128    // persistent recurrence blocks

// ---------------- static device scratch (allocations are forbidden) ----------------
__device__ bf16  g_Xhi[R_ * H_];
__device__ bf16  g_Xlo[R_ * H_];
__device__ bf16  g_WcatT_hi[4 * H_ * H_];   // [n4][k]
__device__ bf16  g_WcatT_lo[4 * H_ * H_];
__device__ float g_bcat[4 * H_];
__device__ float g_XG[(size_t)R_ * 4 * H_]; // precomputed x-gate contributions (+bias)
__device__ float g_Upack[NB * H_ * 32];     // U repacked for recurrence
__device__ float g_Hbuf[H_ * 16];           // h, layout [n][b]
__device__ bf16  g_HShi[R_ * H_];
__device__ bf16  g_HSlo[R_ * H_];
__device__ bf16  g_WoutT_hi[32768000];      // V_*H_, layout [n][k]
__device__ bf16  g_WoutT_lo[32768000];
__device__ unsigned g_ctr[256];             // per-step grid-barrier counters

// ---------------- prep kernels ----------------
__global__ void zero_ctr_kernel() {
    if (threadIdx.x < 256) g_ctr[threadIdx.x] = 0u;
}

__global__ void bcat_kernel(const float* __restrict__ bf_, const float* __restrict__ bi_,
                            const float* __restrict__ bc_, const float* __restrict__ bo_) {
    int i = blockIdx.x * blockDim.x + threadIdx.x;
    if (i < 4 * H_) {
        int g = i >> 10, n = i & (H_ - 1);
        const float* b = (g == 0) ? bf_ : (g == 1) ? bi_ : (g == 2) ? bc_ : bo_;
        g_bcat[i] = b[n];
    }
}

__global__ void gather_split_kernel(const int* __restrict__ tokens,
                                    const float* __restrict__ emb) {
    for (int idx = blockIdx.x * blockDim.x + threadIdx.x; idx < R_ * H_;
         idx += gridDim.x * blockDim.x) {
        int r = idx >> 10, k = idx & (H_ - 1);
        float v = emb[(size_t)tokens[r] * H_ + k];
        bf16 h = __float2bfloat16(v);
        g_Xhi[idx] = h;
        g_Xlo[idx] = __float2bfloat16(v - __bfloat162float(h));
    }
}

// WcatT[n4][k] = w_g[k][n]  (n4 = g*1024 + n)
__global__ void wcatT_split_kernel(const float* __restrict__ wf, const float* __restrict__ wi,
                                   const float* __restrict__ wc, const float* __restrict__ wo) {
    for (int idx = blockIdx.x * blockDim.x + threadIdx.x; idx < 4 * H_ * H_;
         idx += gridDim.x * blockDim.x) {
        int k = idx & 1023;
        int n4 = idx >> 10;
        int g = n4 >> 10, n = n4 & 1023;
        const float* w = (g == 0) ? wf : (g == 1) ? wi : (g == 2) ? wc : wo;
        float v = w[(size_t)k * H_ + n];
        bf16 h = __float2bfloat16(v);
        g_WcatT_hi[idx] = h;
        g_WcatT_lo[idx] = __float2bfloat16(v - __bfloat162float(h));
    }
}

// Tiled transpose+split: WoutT[n][k] = w_out[k][n], both sides coalesced.
__global__ __launch_bounds__(256) void woutT_split_kernel(const float* __restrict__ wout) {
    __shared__ float t[32][33];
    int n0 = blockIdx.x * 32, k0 = blockIdx.y * 32;
    int tx = threadIdx.x, ty = threadIdx.y;  // 32 x 8
#pragma unroll
    for (int i = ty; i < 32; i += 8) t[i][tx] = wout[(size_t)(k0 + i) * V_ + n0 + tx];
    __syncthreads();
#pragma unroll
    for (int i = ty; i < 32; i += 8) {
        float v = t[tx][i];
        bf16 h = __float2bfloat16(v);
        size_t o = (size_t)(n0 + i) * H_ + k0 + tx;
        g_WoutT_hi[o] = h;
        g_WoutT_lo[o] = __float2bfloat16(v - __bfloat162float(h));
    }
}

// Upack[(i*1024 + k)*32 + l] = u_g[k][8*i + j], where g = l>>3, j = l&7
__global__ void pack_u_kernel(const float* __restrict__ uf, const float* __restrict__ ui,
                              const float* __restrict__ uc, const float* __restrict__ uo) {
    for (int idx = blockIdx.x * blockDim.x + threadIdx.x; idx < NB * H_ * 32;
         idx += gridDim.x * blockDim.x) {
        int l = idx & 31;
        int k = (idx >> 5) & 1023;
        int i = idx >> 15;
        int g = l >> 3, j = l & 7;
        const float* u = (g == 0) ? uf : (g == 1) ? ui : (g == 2) ? uc : uo;
        g_Upack[idx] = u[(size_t)k * H_ + 8 * i + j];
    }
}

// ---------------- split-bf16 GEMM (round-3 proven version) ----------------
// C[M,N] = A[M,K]*B^T[N,K] + bias. A,Bt row-major hi/lo. 128x128 tiles, BK=32.
// C = Ah*Bh + Ah*Bl + Al*Bh (fp32 accum), rel err ~1e-5.

__device__ __forceinline__ void mma16816(float c[4], const uint32_t a[4], uint32_t b0,
                                         uint32_t b1) {
    asm volatile(
        "mma.sync.aligned.m16n8k16.row.col.f32.bf16.bf16.f32 "
        "{%0,%1,%2,%3}, {%4,%5,%6,%7}, {%8,%9}, {%0,%1,%2,%3};\n"
        : "+f"(c[0]), "+f"(c[1]), "+f"(c[2]), "+f"(c[3])
        : "r"(a[0]), "r"(a[1]), "r"(a[2]), "r"(a[3]), "r"(b0), "r"(b1));
}

struct Stage {
    uint4 ra[2][2];
    uint4 rb[2][2];
};

__device__ __forceinline__ void g_load(Stage& s, const bf16* __restrict__ Ahi,
                                       const bf16* __restrict__ Alo,
                                       const bf16* __restrict__ Bhi,
                                       const bf16* __restrict__ Blo, int bm0, int bn0, int K,
                                       int k0, int tid) {
#pragma unroll
    for (int q = 0; q < 2; q++) {
        int idx = q * 256 + tid;
        int r = idx >> 2, cg = idx & 3;
        s.ra[0][q] = *(const uint4*)(Ahi + (size_t)(bm0 + r) * K + k0 + cg * 8);
        s.ra[1][q] = *(const uint4*)(Alo + (size_t)(bm0 + r) * K + k0 + cg * 8);
        s.rb[0][q] = *(const uint4*)(Bhi + (size_t)(bn0 + r) * K + k0 + cg * 8);
        s.rb[1][q] = *(const uint4*)(Blo + (size_t)(bn0 + r) * K + k0 + cg * 8);
    }
}

__device__ __forceinline__ void g_store(const Stage& s, bf16 (*As)[128][40], bf16 (*Bs)[128][40],
                                        int tid) {
#pragma unroll
    for (int q = 0; q < 2; q++) {
        int idx = q * 256 + tid;
        int r = idx >> 2, cg = idx & 3;
        *(uint4*)&As[0][r][cg * 8] = s.ra[0][q];
        *(uint4*)&As[1][r][cg * 8] = s.ra[1][q];
        *(uint4*)&Bs[0][r][cg * 8] = s.rb[0][q];
        *(uint4*)&Bs[1][r][cg * 8] = s.rb[1][q];
    }
}

__global__ __launch_bounds__(256) void gemm_split_kernel(
    const bf16* __restrict__ Ahi, const bf16* __restrict__ Alo, const bf16* __restrict__ Bhi,
    const bf16* __restrict__ Blo, const float* __restrict__ bias, float* __restrict__ C, int M,
    int N, int K) {
    __shared__ bf16 As[2][128][40];
    __shared__ bf16 Bs[2][128][40];

    const int tid = threadIdx.x;
    const int bn0 = blockIdx.x * 128;
    const int bm0 = blockIdx.y * 128;
    const int lane = tid & 31, warp = tid >> 5;
    const int wm = warp & 3, wn = warp >> 2;
    const int g = lane >> 2, tg = lane & 3;

    float acc[2][8][4];
#pragma unroll
    for (int mi = 0; mi < 2; mi++)
#pragma unroll
        for (int nj = 0; nj < 8; nj++)
#pragma unroll
            for (int e = 0; e < 4; e++) acc[mi][nj][e] = 0.f;

    Stage st;
    g_load(st, Ahi, Alo, Bhi, Blo, bm0, bn0, K, 0, tid);
    g_store(st, As, Bs, tid);
    __syncthreads();

    const int nk = K / 32;
    for (int kt = 0; kt < nk; kt++) {
        if (kt + 1 < nk) g_load(st, Ahi, Alo, Bhi, Blo, bm0, bn0, K, (kt + 1) * 32, tid);
#pragma unroll
        for (int ks = 0; ks < 32; ks += 16) {
            uint32_t ah[2][4], al[2][4];
#pragma unroll
            for (int mi = 0; mi < 2; mi++) {
                int r0 = wm * 32 + mi * 16 + g;
                ah[mi][0] = *(const uint32_t*)&As[0][r0][ks + 2 * tg];
                ah[mi][1] = *(const uint32_t*)&As[0][r0 + 8][ks + 2 * tg];
                ah[mi][2] = *(const uint32_t*)&As[0][r0][ks + 2 * tg + 8];
                ah[mi][3] = *(const uint32_t*)&As[0][r0 + 8][ks + 2 * tg + 8];
                al[mi][0] = *(const uint32_t*)&As[1][r0][ks + 2 * tg];
                al[mi][1] = *(const uint32_t*)&As[1][r0 + 8][ks + 2 * tg];
                al[mi][2] = *(const uint32_t*)&As[1][r0][ks + 2 * tg + 8];
                al[mi][3] = *(const uint32_t*)&As[1][r0 + 8][ks + 2 * tg + 8];
            }
#pragma unroll
            for (int nj = 0; nj < 8; nj++) {
                int n = wn * 64 + nj * 8 + g;
                uint32_t bh0 = *(const uint32_t*)&Bs[0][n][ks + 2 * tg];
                uint32_t bh1 = *(const uint32_t*)&Bs[0][n][ks + 2 * tg + 8];
                uint32_t bl0 = *(const uint32_t*)&Bs[1][n][ks + 2 * tg];
                uint32_t bl1 = *(const uint32_t*)&Bs[1][n][ks + 2 * tg + 8];
#pragma unroll
                for (int mi = 0; mi < 2; mi++) {
                    mma16816(acc[mi][nj], ah[mi], bh0, bh1);
                    mma16816(acc[mi][nj], ah[mi], bl0, bl1);
                    mma16816(acc[mi][nj], al[mi], bh0, bh1);
                }
            }
        }
        __syncthreads();
        if (kt + 1 < nk) {
            g_store(st, As, Bs, tid);
            __syncthreads();
        }
    }

#pragma unroll
    for (int mi = 0; mi < 2; mi++) {
#pragma unroll
        for (int nj = 0; nj < 8; nj++) {
            int r = bm0 + wm * 32 + mi * 16 + g;
            int nc = bn0 + wn * 64 + nj * 8 + 2 * tg;
            float b0 = bias[nc], b1 = bias[nc + 1];
            float2 v0 = make_float2(acc[mi][nj][0] + b0, acc[mi][nj][1] + b1);
            float2 v1 = make_float2(acc[mi][nj][2] + b0, acc[mi][nj][3] + b1);
            *(float2*)&C[(size_t)r * N + nc] = v0;
            *(float2*)&C[(size_t)(r + 8) * N + nc] = v1;
        }
    }
}

// ---------------- persistent LSTM recurrence (packed f32x2 FMA) ----------------
// 128 blocks x 256 threads, block i owns h-cols [8i, 8i+8).
extern __shared__ float recur_smem[];

__global__ __launch_bounds__(256) void recur_kernel() {
    float* hsm = recur_smem;        // 16384 floats, layout [k][16]
    float* Gs = hsm + 16384;        // 512:  [g][r][j]
    float* red = Gs + 512;          // 512:  kh=1 partials
    float* csm = red + 512;         // 128:  cell state

    const int i = blockIdx.x;
    const int tid = threadIdx.x;
    const int l = tid & 31;
    const int rg = (tid >> 5) & 3;
    const int kh = tid >> 7;
    const int gg = l >> 3, jj = l & 7;

    if (tid < 128) csm[tid] = 0.f;
    const float* up_base = g_Upack + ((size_t)i * 1024 + kh * 512) * 32 + l;
    // h pairs, packed: element k = hsm[(kh*512+k)*16 + rg*4 .. +3]
    const ulonglong2* hp = (const ulonglong2*)(hsm + kh * 512 * 16 + rg * 4);

    for (int t = 0; t < 256; t++) {
        float a0 = 0.f, a1 = 0.f, a2 = 0.f, a3 = 0.f;
        if (t > 0) {
            const float4* src = (const float4*)g_Hbuf;
            float4* dst = (float4*)hsm;
#pragma unroll
            for (int q = 0; q < 16; q++) dst[tid + q * 256] = src[tid + q * 256];
            __syncthreads();
            const float* up = up_base;
            unsigned long long acc01 = 0ull, acc23 = 0ull;  // {0.f,0.f}
#pragma unroll 8
            for (int k = 0; k < 512; k++) {
                float u = up[k * 32];
                unsigned long long u2;
                asm("mov.b64 %0, {%1, %1};" : "=l"(u2) : "f"(u));
                ulonglong2 hv = hp[k * 4];
                asm("fma.rn.f32x2 %0, %1, %2, %0;" : "+l"(acc01) : "l"(hv.x), "l"(u2));
                asm("fma.rn.f32x2 %0, %1, %2, %0;" : "+l"(acc23) : "l"(hv.y), "l"(u2));
            }
            asm("mov.b64 {%0, %1}, %2;" : "=f"(a0), "=f"(a1) : "l"(acc01));
            asm("mov.b64 {%0, %1}, %2;" : "=f"(a2), "=f"(a3) : "l"(acc23));
        }
        if (kh == 1) {
            red[(tid - 128) * 4 + 0] = a0;
            red[(tid - 128) * 4 + 1] = a1;
            red[(tid - 128) * 4 + 2] = a2;
            red[(tid - 128) * 4 + 3] = a3;
        }
        __syncthreads();
        if (kh == 0) {
            a0 += red[tid * 4 + 0];
            a1 += red[tid * 4 + 1];
            a2 += red[tid * 4 + 2];
            a3 += red[tid * 4 + 3];
            float* gp = Gs + gg * 128 + jj;
            gp[(4 * rg + 0) * 8] = a0;
            gp[(4 * rg + 1) * 8] = a1;
            gp[(4 * rg + 2) * 8] = a2;
            gp[(4 * rg + 3) * 8] = a3;
        }
        __syncthreads();
        if (tid < 128) {
            int r = tid >> 3, j = tid & 7;
            int n = 8 * i + j;
            int row = r * 256 + t;
            const float* xg = g_XG + (size_t)row * 4096 + n;
            float pf = Gs[0 * 128 + r * 8 + j] + xg[0];
            float pi = Gs[1 * 128 + r * 8 + j] + xg[1024];
            float pc = Gs[2 * 128 + r * 8 + j] + xg[2048];
            float po = Gs[3 * 128 + r * 8 + j] + xg[3072];
            float f = 1.f / (1.f + expf(-pf));
            float ig = 1.f / (1.f + expf(-pi));
            float cd = tanhf(pc);
            float o = 1.f / (1.f + expf(-po));
            float c = f * csm[tid] + ig * cd;
            csm[tid] = c;
            float h = o * tanhf(c);
            g_Hbuf[n * 16 + r] = h;
            size_t hidx = (size_t)row * 1024 + n;
            bf16 hh = __float2bfloat16(h);
            g_HShi[hidx] = hh;
            g_HSlo[hidx] = __float2bfloat16(h - __bfloat162float(hh));
        }
        if (t < 255) {
            __threadfence();
            __syncthreads();
            if (tid == 0) {
                atomicAdd(&g_ctr[t], 1u);
                while (*((volatile unsigned*)&g_ctr[t]) < (unsigned)NB) {
                }
                __threadfence();
            }
            __syncthreads();
        }
    }
}

// ---------------- launch ----------------
extern "C" void kernel_launch(void* const* d_in, const int* in_sizes, int n_in, void* d_out,
                              int out_size) {
    const int* tokens = (const int*)d_in[0];
    const float* emb = (const float*)d_in[1];
    const float* w_f = (const float*)d_in[2];
    const float* u_f = (const float*)d_in[3];
    const float* b_f = (const float*)d_in[4];
    const float* w_i = (const float*)d_in[5];
    const float* u_i = (const float*)d_in[6];
    const float* b_i = (const float*)d_in[7];
    const float* w_c = (const float*)d_in[8];
    const float* u_c = (const float*)d_in[9];
    const float* b_c = (const float*)d_in[10];
    const float* w_o = (const float*)d_in[11];
    const float* u_o = (const float*)d_in[12];
    const float* b_o = (const float*)d_in[13];
    const float* w_out = (const float*)d_in[14];
    const float* b_out = (const float*)d_in[15];
    float* out = (float*)d_out;

    const int recur_smem_bytes = (16384 + 512 + 512 + 128) * 4;  // 70144
    cudaFuncSetAttribute(recur_kernel, cudaFuncAttributeMaxDynamicSharedMemorySize,
                         recur_smem_bytes);

    void *p_xhi, *p_xlo, *p_wch, *p_wcl, *p_bcat, *p_xg, *p_hshi, *p_hslo, *p_woh, *p_wol;
    cudaGetSymbolAddress(&p_xhi, g_Xhi);
    cudaGetSymbolAddress(&p_xlo, g_Xlo);
    cudaGetSymbolAddress(&p_wch, g_WcatT_hi);
    cudaGetSymbolAddress(&p_wcl, g_WcatT_lo);
    cudaGetSymbolAddress(&p_bcat, g_bcat);
    cudaGetSymbolAddress(&p_xg, g_XG);
    cudaGetSymbolAddress(&p_hshi, g_HShi);
    cudaGetSymbolAddress(&p_hslo, g_HSlo);
    cudaGetSymbolAddress(&p_woh, g_WoutT_hi);
    cudaGetSymbolAddress(&p_wol, g_WoutT_lo);

    // Launch order arranged so the XG GEMM is my 4th launch -> ncu-profiled slot.
    bcat_kernel<<<16, 256>>>(b_f, b_i, b_c, b_o);                     // idx 0
    gather_split_kernel<<<4096, 256>>>(tokens, emb);                  // idx 1
    wcatT_split_kernel<<<4096, 256>>>(w_f, w_i, w_c, w_o);            // idx 2

    // XG = X @ Wcat + bcat   (M=4096, N=4096, K=1024)                // idx 3 (profiled)
    gemm_split_kernel<<<dim3(4096 / 128, 4096 / 128), 256>>>(
        (const bf16*)p_xhi, (const bf16*)p_xlo, (const bf16*)p_wch, (const bf16*)p_wcl,
        (const float*)p_bcat, (float*)p_xg, R_, 4 * H_, H_);

    zero_ctr_kernel<<<1, 256>>>();                                    // idx 4
    pack_u_kernel<<<4096, 256>>>(u_f, u_i, u_c, u_o);                 // idx 5
    woutT_split_kernel<<<dim3(V_ / 32, H_ / 32), dim3(32, 8)>>>(w_out);  // idx 6

    // sequential LSTM recurrence (persistent, 1 grid barrier per step)
    recur_kernel<<<NB, 256, recur_smem_bytes>>>();                    // idx 7

    // logits = HS @ w_out + b_out   (M=4096, N=32000, K=1024)
    gemm_split_kernel<<<dim3(V_ / 128, R_ / 128), 256>>>(             // idx 8
        (const bf16*)p_hshi, (const bf16*)p_hslo, (const bf16*)p_woh, (const bf16*)p_wol, b_out,
        out, R_, V_, H_);
}

// round 11
// speedup vs baseline: 2.3262x; 1.6515x over previous
#include <cuda_runtime.h>
#include <cuda_bf16.h>
#include <cstdint>

typedef __nv_bfloat16 bf16;

#define H_ 1024
#define V_ 32000
#define B_ 16
#define T_ 256
#define R_ 4096   // B_*T_
#define NB 128    // persistent recurrence blocks

// ---------------- static device scratch (allocations are forbidden) ----------------
__device__ bf16  g_Xhi[R_ * H_];
__device__ bf16  g_Xlo[R_ * H_];
__device__ bf16  g_WcatT_hi[4 * H_ * H_];   // [n4][k]
__device__ bf16  g_WcatT_lo[4 * H_ * H_];
__device__ float g_bcat[4 * H_];
__device__ float g_XG[(size_t)R_ * 4 * H_]; // precomputed x-gate contributions (+bias)
__device__ float g_Upack[NB * H_ * 32];     // U repacked for recurrence
__device__ float g_Hbuf[H_ * 16];           // h, layout [n][b]
__device__ bf16  g_HShi[R_ * H_];
__device__ bf16  g_HSlo[R_ * H_];
__device__ bf16  g_WoutT_hi[32768000];      // V_*H_, layout [n][k]
__device__ bf16  g_WoutT_lo[32768000];
__device__ unsigned g_ctr[256];             // per-step grid-barrier counters

// ---------------- fused prep kernel ----------------
// gather+split X, transpose+split Wcat, pack U, build bcat, zero barrier ctrs.
__global__ void prep_all_kernel(const int* __restrict__ tokens, const float* __restrict__ emb,
                                const float* __restrict__ wf, const float* __restrict__ wi,
                                const float* __restrict__ wc, const float* __restrict__ wo,
                                const float* __restrict__ uf, const float* __restrict__ ui,
                                const float* __restrict__ uc, const float* __restrict__ uo,
                                const float* __restrict__ bf_, const float* __restrict__ bi_,
                                const float* __restrict__ bc_, const float* __restrict__ bo_) {
    const int gstride = gridDim.x * blockDim.x;
    const int gtid = blockIdx.x * blockDim.x + threadIdx.x;

    if (gtid < 256) g_ctr[gtid] = 0u;
    if (gtid < 4 * H_) {
        int g = gtid >> 10, n = gtid & (H_ - 1);
        const float* b = (g == 0) ? bf_ : (g == 1) ? bi_ : (g == 2) ? bc_ : bo_;
        g_bcat[gtid] = b[n];
    }

    // gather + split X
    for (int idx = gtid; idx < R_ * H_; idx += gstride) {
        int r = idx >> 10, k = idx & (H_ - 1);
        float v = emb[(size_t)tokens[r] * H_ + k];
        bf16 h = __float2bfloat16(v);
        g_Xhi[idx] = h;
        g_Xlo[idx] = __float2bfloat16(v - __bfloat162float(h));
    }

    // WcatT[n4][k] = w_g[k][n]
    for (int idx = gtid; idx < 4 * H_ * H_; idx += gstride) {
        int k = idx & 1023;
        int n4 = idx >> 10;
        int g = n4 >> 10, n = n4 & 1023;
        const float* w = (g == 0) ? wf : (g == 1) ? wi : (g == 2) ? wc : wo;
        float v = w[(size_t)k * H_ + n];
        bf16 h = __float2bfloat16(v);
        g_WcatT_hi[idx] = h;
        g_WcatT_lo[idx] = __float2bfloat16(v - __bfloat162float(h));
    }

    // Upack[(i*1024 + k)*32 + l] = u_g[k][8*i + j],  g = l>>3, j = l&7
    for (int idx = gtid; idx < NB * H_ * 32; idx += gstride) {
        int l = idx & 31;
        int k = (idx >> 5) & 1023;
        int i = idx >> 15;
        int g = l >> 3, j = l & 7;
        const float* u = (g == 0) ? uf : (g == 1) ? ui : (g == 2) ? uc : uo;
        g_Upack[idx] = u[(size_t)k * H_ + 8 * i + j];
    }
}

// Tiled transpose+split: WoutT[n][k] = w_out[k][n], both sides coalesced.
__global__ __launch_bounds__(256) void woutT_split_kernel(const float* __restrict__ wout) {
    __shared__ float t[32][33];
    int n0 = blockIdx.x * 32, k0 = blockIdx.y * 32;
    int tx = threadIdx.x, ty = threadIdx.y;  // 32 x 8
#pragma unroll
    for (int i = ty; i < 32; i += 8) t[i][tx] = wout[(size_t)(k0 + i) * V_ + n0 + tx];
    __syncthreads();
#pragma unroll
    for (int i = ty; i < 32; i += 8) {
        float v = t[tx][i];
        bf16 h = __float2bfloat16(v);
        size_t o = (size_t)(n0 + i) * H_ + k0 + tx;
        g_WoutT_hi[o] = h;
        g_WoutT_lo[o] = __float2bfloat16(v - __bfloat162float(h));
    }
}

// ---------------- split-bf16 GEMM (round-3 proven version, unchanged) ----------------
__device__ __forceinline__ void mma16816(float c[4], const uint32_t a[4], uint32_t b0,
                                         uint32_t b1) {
    asm volatile(
        "mma.sync.aligned.m16n8k16.row.col.f32.bf16.bf16.f32 "
        "{%0,%1,%2,%3}, {%4,%5,%6,%7}, {%8,%9}, {%0,%1,%2,%3};\n"
        : "+f"(c[0]), "+f"(c[1]), "+f"(c[2]), "+f"(c[3])
        : "r"(a[0]), "r"(a[1]), "r"(a[2]), "r"(a[3]), "r"(b0), "r"(b1));
}

struct Stage {
    uint4 ra[2][2];
    uint4 rb[2][2];
};

__device__ __forceinline__ void g_load(Stage& s, const bf16* __restrict__ Ahi,
                                       const bf16* __restrict__ Alo,
                                       const bf16* __restrict__ Bhi,
                                       const bf16* __restrict__ Blo, int bm0, int bn0, int K,
                                       int k0, int tid) {
#pragma unroll
    for (int q = 0; q < 2; q++) {
        int idx = q * 256 + tid;
        int r = idx >> 2, cg = idx & 3;
        s.ra[0][q] = *(const uint4*)(Ahi + (size_t)(bm0 + r) * K + k0 + cg * 8);
        s.ra[1][q] = *(const uint4*)(Alo + (size_t)(bm0 + r) * K + k0 + cg * 8);
        s.rb[0][q] = *(const uint4*)(Bhi + (size_t)(bn0 + r) * K + k0 + cg * 8);
        s.rb[1][q] = *(const uint4*)(Blo + (size_t)(bn0 + r) * K + k0 + cg * 8);
    }
}

__device__ __forceinline__ void g_store(const Stage& s, bf16 (*As)[128][40], bf16 (*Bs)[128][40],
                                        int tid) {
#pragma unroll
    for (int q = 0; q < 2; q++) {
        int idx = q * 256 + tid;
        int r = idx >> 2, cg = idx & 3;
        *(uint4*)&As[0][r][cg * 8] = s.ra[0][q];
        *(uint4*)&As[1][r][cg * 8] = s.ra[1][q];
        *(uint4*)&Bs[0][r][cg * 8] = s.rb[0][q];
        *(uint4*)&Bs[1][r][cg * 8] = s.rb[1][q];
    }
}

__global__ __launch_bounds__(256) void gemm_split_kernel(
    const bf16* __restrict__ Ahi, const bf16* __restrict__ Alo, const bf16* __restrict__ Bhi,
    const bf16* __restrict__ Blo, const float* __restrict__ bias, float* __restrict__ C, int M,
    int N, int K) {
    __shared__ bf16 As[2][128][40];
    __shared__ bf16 Bs[2][128][40];

    const int tid = threadIdx.x;
    const int bn0 = blockIdx.x * 128;
    const int bm0 = blockIdx.y * 128;
    const int lane = tid & 31, warp = tid >> 5;
    const int wm = warp & 3, wn = warp >> 2;
    const int g = lane >> 2, tg = lane & 3;

    float acc[2][8][4];
#pragma unroll
    for (int mi = 0; mi < 2; mi++)
#pragma unroll
        for (int nj = 0; nj < 8; nj++)
#pragma unroll
            for (int e = 0; e < 4; e++) acc[mi][nj][e] = 0.f;

    Stage st;
    g_load(st, Ahi, Alo, Bhi, Blo, bm0, bn0, K, 0, tid);
    g_store(st, As, Bs, tid);
    __syncthreads();

    const int nk = K / 32;
    for (int kt = 0; kt < nk; kt++) {
        if (kt + 1 < nk) g_load(st, Ahi, Alo, Bhi, Blo, bm0, bn0, K, (kt + 1) * 32, tid);
#pragma unroll
        for (int ks = 0; ks < 32; ks += 16) {
            uint32_t ah[2][4], al[2][4];
#pragma unroll
            for (int mi = 0; mi < 2; mi++) {
                int r0 = wm * 32 + mi * 16 + g;
                ah[mi][0] = *(const uint32_t*)&As[0][r0][ks + 2 * tg];
                ah[mi][1] = *(const uint32_t*)&As[0][r0 + 8][ks + 2 * tg];
                ah[mi][2] = *(const uint32_t*)&As[0][r0][ks + 2 * tg + 8];
                ah[mi][3] = *(const uint32_t*)&As[0][r0 + 8][ks + 2 * tg + 8];
                al[mi][0] = *(const uint32_t*)&As[1][r0][ks + 2 * tg];
                al[mi][1] = *(const uint32_t*)&As[1][r0 + 8][ks + 2 * tg];
                al[mi][2] = *(const uint32_t*)&As[1][r0][ks + 2 * tg + 8];
                al[mi][3] = *(const uint32_t*)&As[1][r0 + 8][ks + 2 * tg + 8];
            }
#pragma unroll
            for (int nj = 0; nj < 8; nj++) {
                int n = wn * 64 + nj * 8 + g;
                uint32_t bh0 = *(const uint32_t*)&Bs[0][n][ks + 2 * tg];
                uint32_t bh1 = *(const uint32_t*)&Bs[0][n][ks + 2 * tg + 8];
                uint32_t bl0 = *(const uint32_t*)&Bs[1][n][ks + 2 * tg];
                uint32_t bl1 = *(const uint32_t*)&Bs[1][n][ks + 2 * tg + 8];
#pragma unroll
                for (int mi = 0; mi < 2; mi++) {
                    mma16816(acc[mi][nj], ah[mi], bh0, bh1);
                    mma16816(acc[mi][nj], ah[mi], bl0, bl1);
                    mma16816(acc[mi][nj], al[mi], bh0, bh1);
                }
            }
        }
        __syncthreads();
        if (kt + 1 < nk) {
            g_store(st, As, Bs, tid);
            __syncthreads();
        }
    }

#pragma unroll
    for (int mi = 0; mi < 2; mi++) {
#pragma unroll
        for (int nj = 0; nj < 8; nj++) {
            int r = bm0 + wm * 32 + mi * 16 + g;
            int nc = bn0 + wn * 64 + nj * 8 + 2 * tg;
            float b0 = bias[nc], b1 = bias[nc + 1];
            float2 v0 = make_float2(acc[mi][nj][0] + b0, acc[mi][nj][1] + b1);
            float2 v1 = make_float2(acc[mi][nj][2] + b0, acc[mi][nj][3] + b1);
            *(float2*)&C[(size_t)r * N + nc] = v0;
            *(float2*)&C[(size_t)(r + 8) * N + nc] = v1;
        }
    }
}

// ---------------- persistent LSTM recurrence (U staged in SMEM) ----------------
// 128 blocks x 256 threads, block i owns h-cols [8i, 8i+8).
// SMEM: U slice 128KB (immune to the per-step CCTL.IVALL L1 flush from __threadfence)
//       + h 64KB + reduction buffers. 201216 bytes total, 1 block/SM.
extern __shared__ float recur_smem[];

__global__ __launch_bounds__(256) void recur_kernel() {
    float* usm = recur_smem;        // 32768 floats: block's U slice, [k][32]
    float* hsm = usm + 32768;       // 16384 floats: h, layout [k][16]
    float* Gs = hsm + 16384;        // 512:  [g][r][j]
    float* red = Gs + 512;          // 512:  kh=1 partials
    float* csm = red + 512;         // 128:  cell state

    const int i = blockIdx.x;
    const int tid = threadIdx.x;
    const int l = tid & 31;
    const int rg = (tid >> 5) & 3;
    const int kh = tid >> 7;
    const int gg = l >> 3, jj = l & 7;

    // one-time: stage this block's U slice (1024 x 32 floats) into smem
    {
        const float4* src = (const float4*)(g_Upack + (size_t)i * 1024 * 32);
        float4* dst = (float4*)usm;
#pragma unroll
        for (int q = 0; q < 32; q++) dst[tid + q * 256] = src[tid + q * 256];
    }
    if (tid < 128) csm[tid] = 0.f;
    __syncthreads();

    const float* up_base = usm + (kh * 512) * 32 + l;
    const ulonglong2* hp = (const ulonglong2*)(hsm + kh * 512 * 16 + rg * 4);

    for (int t = 0; t < 256; t++) {
        float a0 = 0.f, a1 = 0.f, a2 = 0.f, a3 = 0.f;
        if (t > 0) {
            const float4* src = (const float4*)g_Hbuf;
            float4* dst = (float4*)hsm;
#pragma unroll
            for (int q = 0; q < 16; q++) dst[tid + q * 256] = src[tid + q * 256];
            __syncthreads();
            const float* up = up_base;
            unsigned long long acc01 = 0ull, acc23 = 0ull;  // {0.f,0.f}
#pragma unroll 8
            for (int k = 0; k < 512; k++) {
                float u = up[k * 32];
                unsigned long long u2;
                asm("mov.b64 %0, {%1, %1};" : "=l"(u2) : "f"(u));
                ulonglong2 hv = hp[k * 4];
                asm("fma.rn.f32x2 %0, %1, %2, %0;" : "+l"(acc01) : "l"(hv.x), "l"(u2));
                asm("fma.rn.f32x2 %0, %1, %2, %0;" : "+l"(acc23) : "l"(hv.y), "l"(u2));
            }
            asm("mov.b64 {%0, %1}, %2;" : "=f"(a0), "=f"(a1) : "l"(acc01));
            asm("mov.b64 {%0, %1}, %2;" : "=f"(a2), "=f"(a3) : "l"(acc23));
        }
        if (kh == 1) {
            red[(tid - 128) * 4 + 0] = a0;
            red[(tid - 128) * 4 + 1] = a1;
            red[(tid - 128) * 4 + 2] = a2;
            red[(tid - 128) * 4 + 3] = a3;
        }
        __syncthreads();
        if (kh == 0) {
            a0 += red[tid * 4 + 0];
            a1 += red[tid * 4 + 1];
            a2 += red[tid * 4 + 2];
            a3 += red[tid * 4 + 3];
            float* gp = Gs + gg * 128 + jj;
            gp[(4 * rg + 0) * 8] = a0;
            gp[(4 * rg + 1) * 8] = a1;
            gp[(4 * rg + 2) * 8] = a2;
            gp[(4 * rg + 3) * 8] = a3;
        }
        __syncthreads();
        if (tid < 128) {
            int r = tid >> 3, j = tid & 7;
            int n = 8 * i + j;
            int row = r * 256 + t;
            const float* xg = g_XG + (size_t)row * 4096 + n;
            float pf = Gs[0 * 128 + r * 8 + j] + xg[0];
            float pi = Gs[1 * 128 + r * 8 + j] + xg[1024];
            float pc = Gs[2 * 128 + r * 8 + j] + xg[2048];
            float po = Gs[3 * 128 + r * 8 + j] + xg[3072];
            float f = 1.f / (1.f + expf(-pf));
            float ig = 1.f / (1.f + expf(-pi));
            float cd = tanhf(pc);
            float o = 1.f / (1.f + expf(-po));
            float c = f * csm[tid] + ig * cd;
            csm[tid] = c;
            float h = o * tanhf(c);
            g_Hbuf[n * 16 + r] = h;
            size_t hidx = (size_t)row * 1024 + n;
            bf16 hh = __float2bfloat16(h);
            g_HShi[hidx] = hh;
            g_HSlo[hidx] = __float2bfloat16(h - __bfloat162float(hh));
        }
        if (t < 255) {
            __threadfence();
            __syncthreads();
            if (tid == 0) {
                atomicAdd(&g_ctr[t], 1u);
                while (*((volatile unsigned*)&g_ctr[t]) < (unsigned)NB) {
                }
                __threadfence();
            }
            __syncthreads();
        }
    }
}

// ---------------- launch ----------------
extern "C" void kernel_launch(void* const* d_in, const int* in_sizes, int n_in, void* d_out,
                              int out_size) {
    const int* tokens = (const int*)d_in[0];
    const float* emb = (const float*)d_in[1];
    const float* w_f = (const float*)d_in[2];
    const float* u_f = (const float*)d_in[3];
    const float* b_f = (const float*)d_in[4];
    const float* w_i = (const float*)d_in[5];
    const float* u_i = (const float*)d_in[6];
    const float* b_i = (const float*)d_in[7];
    const float* w_c = (const float*)d_in[8];
    const float* u_c = (const float*)d_in[9];
    const float* b_c = (const float*)d_in[10];
    const float* w_o = (const float*)d_in[11];
    const float* u_o = (const float*)d_in[12];
    const float* b_o = (const float*)d_in[13];
    const float* w_out = (const float*)d_in[14];
    const float* b_out = (const float*)d_in[15];
    float* out = (float*)d_out;

    const int recur_smem_bytes = (32768 + 16384 + 512 + 512 + 128) * 4;  // 201216
    cudaFuncSetAttribute(recur_kernel, cudaFuncAttributeMaxDynamicSharedMemorySize,
                         recur_smem_bytes);

    void *p_xhi, *p_xlo, *p_wch, *p_wcl, *p_bcat, *p_xg, *p_hshi, *p_hslo, *p_woh, *p_wol;
    cudaGetSymbolAddress(&p_xhi, g_Xhi);
    cudaGetSymbolAddress(&p_xlo, g_Xlo);
    cudaGetSymbolAddress(&p_wch, g_WcatT_hi);
    cudaGetSymbolAddress(&p_wcl, g_WcatT_lo);
    cudaGetSymbolAddress(&p_bcat, g_bcat);
    cudaGetSymbolAddress(&p_xg, g_XG);
    cudaGetSymbolAddress(&p_hshi, g_HShi);
    cudaGetSymbolAddress(&p_hslo, g_HSlo);
    cudaGetSymbolAddress(&p_woh, g_WoutT_hi);
    cudaGetSymbolAddress(&p_wol, g_WoutT_lo);

    // idx 0: all prep (gather, wcatT, pack_u, bcat, barrier ctrs)
    prep_all_kernel<<<4096, 256>>>(tokens, emb, w_f, w_i, w_c, w_o, u_f, u_i, u_c, u_o, b_f,
                                   b_i, b_c, b_o);

    // idx 1: XG = X @ Wcat + bcat   (M=4096, N=4096, K=1024)
    gemm_split_kernel<<<dim3(4096 / 128, 4096 / 128), 256>>>(
        (const bf16*)p_xhi, (const bf16*)p_xlo, (const bf16*)p_wch, (const bf16*)p_wcl,
        (const float*)p_bcat, (float*)p_xg, R_, 4 * H_, H_);

    // idx 2: w_out transpose+split (independent of recurrence)
    woutT_split_kernel<<<dim3(V_ / 32, H_ / 32), dim3(32, 8)>>>(w_out);

    // idx 3 (ncu-profiled slot): sequential LSTM recurrence
    recur_kernel<<<NB, 256, recur_smem_bytes>>>();

    // idx 4: logits = HS @ w_out + b_out   (M=4096, N=32000, K=1024)
    gemm_split_kernel<<<dim3(V_ / 128, R_ / 128), 256>>>(
        (const bf16*)p_hshi, (const bf16*)p_hslo, (const bf16*)p_woh, (const bf16*)p_wol, b_out,
        out, R_, V_, H_);
}

// round 12
// speedup vs baseline: 2.3766x; 1.0217x over previous
#include <cuda_runtime.h>
#include <cuda_bf16.h>
#include <cstdint>

typedef __nv_bfloat16 bf16;

#define H_ 1024
#define V_ 32000
#define B_ 16
#define T_ 256
#define R_ 4096   // B_*T_
#define NB 128    // persistent recurrence blocks

// ---------------- static device scratch (allocations are forbidden) ----------------
__device__ bf16  g_Xhi[R_ * H_];
__device__ bf16  g_Xlo[R_ * H_];
__device__ bf16  g_WcatT_hi[4 * H_ * H_];   // [n4][k]
__device__ bf16  g_WcatT_lo[4 * H_ * H_];
__device__ float g_bcat[4 * H_];
__device__ float g_XG[(size_t)R_ * 4 * H_]; // precomputed x-gate contributions (+bias)
__device__ float g_Upack[NB * H_ * 32];     // U repacked for recurrence
__device__ float g_Hbuf[H_ * 16];           // h, layout [n][b]
__device__ bf16  g_HShi[R_ * H_];
__device__ bf16  g_HSlo[R_ * H_];
__device__ bf16  g_WoutT_hi[32768000];      // V_*H_, layout [n][k]
__device__ bf16  g_WoutT_lo[32768000];
__device__ unsigned g_ctr[256];             // per-step grid-barrier counters

// ---------------- prep kernels (split in two so the XG GEMM lands in ncu's slot) ----------------
__global__ void prep_a_kernel(const int* __restrict__ tokens, const float* __restrict__ emb,
                              const float* __restrict__ bf_, const float* __restrict__ bi_,
                              const float* __restrict__ bc_, const float* __restrict__ bo_) {
    const int gstride = gridDim.x * blockDim.x;
    const int gtid = blockIdx.x * blockDim.x + threadIdx.x;

    if (gtid < 256) g_ctr[gtid] = 0u;
    if (gtid < 4 * H_) {
        int g = gtid >> 10, n = gtid & (H_ - 1);
        const float* b = (g == 0) ? bf_ : (g == 1) ? bi_ : (g == 2) ? bc_ : bo_;
        g_bcat[gtid] = b[n];
    }
    for (int idx = gtid; idx < R_ * H_; idx += gstride) {
        int r = idx >> 10, k = idx & (H_ - 1);
        float v = emb[(size_t)tokens[r] * H_ + k];
        bf16 h = __float2bfloat16(v);
        g_Xhi[idx] = h;
        g_Xlo[idx] = __float2bfloat16(v - __bfloat162float(h));
    }
}

__global__ void prep_b_kernel(const float* __restrict__ wf, const float* __restrict__ wi,
                              const float* __restrict__ wc, const float* __restrict__ wo,
                              const float* __restrict__ uf, const float* __restrict__ ui,
                              const float* __restrict__ uc, const float* __restrict__ uo) {
    const int gstride = gridDim.x * blockDim.x;
    const int gtid = blockIdx.x * blockDim.x + threadIdx.x;

    // WcatT[n4][k] = w_g[k][n]
    for (int idx = gtid; idx < 4 * H_ * H_; idx += gstride) {
        int k = idx & 1023;
        int n4 = idx >> 10;
        int g = n4 >> 10, n = n4 & 1023;
        const float* w = (g == 0) ? wf : (g == 1) ? wi : (g == 2) ? wc : wo;
        float v = w[(size_t)k * H_ + n];
        bf16 h = __float2bfloat16(v);
        g_WcatT_hi[idx] = h;
        g_WcatT_lo[idx] = __float2bfloat16(v - __bfloat162float(h));
    }
    // Upack[(i*1024 + k)*32 + l] = u_g[k][8*i + j],  g = l>>3, j = l&7
    for (int idx = gtid; idx < NB * H_ * 32; idx += gstride) {
        int l = idx & 31;
        int k = (idx >> 5) & 1023;
        int i = idx >> 15;
        int g = l >> 3, j = l & 7;
        const float* u = (g == 0) ? uf : (g == 1) ? ui : (g == 2) ? uc : uo;
        g_Upack[idx] = u[(size_t)k * H_ + 8 * i + j];
    }
}

// Tiled transpose+split: WoutT[n][k] = w_out[k][n], both sides coalesced.
__global__ __launch_bounds__(256) void woutT_split_kernel(const float* __restrict__ wout) {
    __shared__ float t[32][33];
    int n0 = blockIdx.x * 32, k0 = blockIdx.y * 32;
    int tx = threadIdx.x, ty = threadIdx.y;  // 32 x 8
#pragma unroll
    for (int i = ty; i < 32; i += 8) t[i][tx] = wout[(size_t)(k0 + i) * V_ + n0 + tx];
    __syncthreads();
#pragma unroll
    for (int i = ty; i < 32; i += 8) {
        float v = t[tx][i];
        bf16 h = __float2bfloat16(v);
        size_t o = (size_t)(n0 + i) * H_ + k0 + tx;
        g_WoutT_hi[o] = h;
        g_WoutT_lo[o] = __float2bfloat16(v - __bfloat162float(h));
    }
}

// ---------------- split-bf16 GEMM: 128x64 tiles, 2 blocks/SM ----------------
// C[M,N] = A[M,K]*B^T[N,K] + bias. C = Ah*Bh + Ah*Bl + Al*Bh, fp32 accum.
__device__ __forceinline__ void mma16816(float c[4], const uint32_t a[4], uint32_t b0,
                                         uint32_t b1) {
    asm volatile(
        "mma.sync.aligned.m16n8k16.row.col.f32.bf16.bf16.f32 "
        "{%0,%1,%2,%3}, {%4,%5,%6,%7}, {%8,%9}, {%0,%1,%2,%3};\n"
        : "+f"(c[0]), "+f"(c[1]), "+f"(c[2]), "+f"(c[3])
        : "r"(a[0]), "r"(a[1]), "r"(a[2]), "r"(a[3]), "r"(b0), "r"(b1));
}

struct Stage {
    uint4 ra[2][2];  // [hi/lo][q]  A: 128 rows
    uint4 rb[2];     // [hi/lo]     B: 64 rows
};

__device__ __forceinline__ void g_load(Stage& s, const bf16* __restrict__ Ahi,
                                       const bf16* __restrict__ Alo,
                                       const bf16* __restrict__ Bhi,
                                       const bf16* __restrict__ Blo, int bm0, int bn0, int K,
                                       int k0, int tid) {
#pragma unroll
    for (int q = 0; q < 2; q++) {
        int idx = q * 256 + tid;
        int r = idx >> 2, cg = idx & 3;
        s.ra[0][q] = *(const uint4*)(Ahi + (size_t)(bm0 + r) * K + k0 + cg * 8);
        s.ra[1][q] = *(const uint4*)(Alo + (size_t)(bm0 + r) * K + k0 + cg * 8);
    }
    int r = tid >> 2, cg = tid & 3;
    s.rb[0] = *(const uint4*)(Bhi + (size_t)(bn0 + r) * K + k0 + cg * 8);
    s.rb[1] = *(const uint4*)(Blo + (size_t)(bn0 + r) * K + k0 + cg * 8);
}

__device__ __forceinline__ void g_store(const Stage& s, bf16 (*As)[128][40], bf16 (*Bs)[64][40],
                                        int tid) {
#pragma unroll
    for (int q = 0; q < 2; q++) {
        int idx = q * 256 + tid;
        int r = idx >> 2, cg = idx & 3;
        *(uint4*)&As[0][r][cg * 8] = s.ra[0][q];
        *(uint4*)&As[1][r][cg * 8] = s.ra[1][q];
    }
    int r = tid >> 2, cg = tid & 3;
    *(uint4*)&Bs[0][r][cg * 8] = s.rb[0];
    *(uint4*)&Bs[1][r][cg * 8] = s.rb[1];
}

__global__ __launch_bounds__(256, 2) void gemm_split_kernel(
    const bf16* __restrict__ Ahi, const bf16* __restrict__ Alo, const bf16* __restrict__ Bhi,
    const bf16* __restrict__ Blo, const float* __restrict__ bias, float* __restrict__ C, int M,
    int N, int K) {
    __shared__ bf16 As[2][128][40];
    __shared__ bf16 Bs[2][64][40];

    const int tid = threadIdx.x;
    const int bn0 = blockIdx.x * 64;
    const int bm0 = blockIdx.y * 128;
    const int lane = tid & 31, warp = tid >> 5;
    const int wm = warp & 3, wn = warp >> 2;
    const int g = lane >> 2, tg = lane & 3;

    float acc[2][4][4];
#pragma unroll
    for (int mi = 0; mi < 2; mi++)
#pragma unroll
        for (int nj = 0; nj < 4; nj++)
#pragma unroll
            for (int e = 0; e < 4; e++) acc[mi][nj][e] = 0.f;

    Stage st;
    g_load(st, Ahi, Alo, Bhi, Blo, bm0, bn0, K, 0, tid);
    g_store(st, As, Bs, tid);
    __syncthreads();

    const int nk = K / 32;
    for (int kt = 0; kt < nk; kt++) {
        if (kt + 1 < nk) g_load(st, Ahi, Alo, Bhi, Blo, bm0, bn0, K, (kt + 1) * 32, tid);
#pragma unroll
        for (int ks = 0; ks < 32; ks += 16) {
            uint32_t ah[2][4], al[2][4];
#pragma unroll
            for (int mi = 0; mi < 2; mi++) {
                int r0 = wm * 32 + mi * 16 + g;
                ah[mi][0] = *(const uint32_t*)&As[0][r0][ks + 2 * tg];
                ah[mi][1] = *(const uint32_t*)&As[0][r0 + 8][ks + 2 * tg];
                ah[mi][2] = *(const uint32_t*)&As[0][r0][ks + 2 * tg + 8];
                ah[mi][3] = *(const uint32_t*)&As[0][r0 + 8][ks + 2 * tg + 8];
                al[mi][0] = *(const uint32_t*)&As[1][r0][ks + 2 * tg];
                al[mi][1] = *(const uint32_t*)&As[1][r0 + 8][ks + 2 * tg];
                al[mi][2] = *(const uint32_t*)&As[1][r0][ks + 2 * tg + 8];
                al[mi][3] = *(const uint32_t*)&As[1][r0 + 8][ks + 2 * tg + 8];
            }
#pragma unroll
            for (int nj = 0; nj < 4; nj++) {
                int n = wn * 32 + nj * 8 + g;
                uint32_t bh0 = *(const uint32_t*)&Bs[0][n][ks + 2 * tg];
                uint32_t bh1 = *(const uint32_t*)&Bs[0][n][ks + 2 * tg + 8];
                uint32_t bl0 = *(const uint32_t*)&Bs[1][n][ks + 2 * tg];
                uint32_t bl1 = *(const uint32_t*)&Bs[1][n][ks + 2 * tg + 8];
#pragma unroll
                for (int mi = 0; mi < 2; mi++) {
                    mma16816(acc[mi][nj], ah[mi], bh0, bh1);
                    mma16816(acc[mi][nj], ah[mi], bl0, bl1);
                    mma16816(acc[mi][nj], al[mi], bh0, bh1);
                }
            }
        }
        __syncthreads();
        if (kt + 1 < nk) {
            g_store(st, As, Bs, tid);
            __syncthreads();
        }
    }

#pragma unroll
    for (int mi = 0; mi < 2; mi++) {
#pragma unroll
        for (int nj = 0; nj < 4; nj++) {
            int r = bm0 + wm * 32 + mi * 16 + g;
            int nc = bn0 + wn * 32 + nj * 8 + 2 * tg;
            float b0 = bias[nc], b1 = bias[nc + 1];
            float2 v0 = make_float2(acc[mi][nj][0] + b0, acc[mi][nj][1] + b1);
            float2 v1 = make_float2(acc[mi][nj][2] + b0, acc[mi][nj][3] + b1);
            *(float2*)&C[(size_t)r * N + nc] = v0;
            *(float2*)&C[(size_t)(r + 8) * N + nc] = v1;
        }
    }
}

// ---------------- persistent LSTM recurrence (U in SMEM, fence-free grid barrier) ----------------
extern __shared__ float recur_smem[];

__global__ __launch_bounds__(256) void recur_kernel() {
    float* usm = recur_smem;        // 32768 floats: block's U slice, [k][32]
    float* hsm = usm + 32768;       // 16384 floats: h, layout [k][16]
    float* Gs = hsm + 16384;        // 512:  [g][r][j]
    float* red = Gs + 512;          // 512:  kh=1 partials
    float* csm = red + 512;         // 128:  cell state

    const int i = blockIdx.x;
    const int tid = threadIdx.x;
    const int l = tid & 31;
    const int rg = (tid >> 5) & 3;
    const int kh = tid >> 7;
    const int gg = l >> 3, jj = l & 7;

    // one-time: stage this block's U slice (1024 x 32 floats) into smem
    {
        const float4* src = (const float4*)(g_Upack + (size_t)i * 1024 * 32);
        float4* dst = (float4*)usm;
#pragma unroll
        for (int q = 0; q < 32; q++) dst[tid + q * 256] = src[tid + q * 256];
    }
    if (tid < 128) csm[tid] = 0.f;
    __syncthreads();

    const float* up_base = usm + (kh * 512) * 32 + l;
    const ulonglong2* hp = (const ulonglong2*)(hsm + kh * 512 * 16 + rg * 4);

    for (int t = 0; t < 256; t++) {
        float a0 = 0.f, a1 = 0.f, a2 = 0.f, a3 = 0.f;
        if (t > 0) {
            const float4* src = (const float4*)g_Hbuf;
            float4* dst = (float4*)hsm;
#pragma unroll
            for (int q = 0; q < 16; q++) dst[tid + q * 256] = src[tid + q * 256];
            __syncthreads();
            const float* up = up_base;
            unsigned long long acc01 = 0ull, acc23 = 0ull;  // {0.f,0.f}
#pragma unroll 8
            for (int k = 0; k < 512; k++) {
                float u = up[k * 32];
                unsigned long long u2;
                asm("mov.b64 %0, {%1, %1};" : "=l"(u2) : "f"(u));
                ulonglong2 hv = hp[k * 4];
                asm("fma.rn.f32x2 %0, %1, %2, %0;" : "+l"(acc01) : "l"(hv.x), "l"(u2));
                asm("fma.rn.f32x2 %0, %1, %2, %0;" : "+l"(acc23) : "l"(hv.y), "l"(u2));
            }
            asm("mov.b64 {%0, %1}, %2;" : "=f"(a0), "=f"(a1) : "l"(acc01));
            asm("mov.b64 {%0, %1}, %2;" : "=f"(a2), "=f"(a3) : "l"(acc23));
        }
        if (kh == 1) {
            red[(tid - 128) * 4 + 0] = a0;
            red[(tid - 128) * 4 + 1] = a1;
            red[(tid - 128) * 4 + 2] = a2;
            red[(tid - 128) * 4 + 3] = a3;
        }
        __syncthreads();
        if (kh == 0) {
            a0 += red[tid * 4 + 0];
            a1 += red[tid * 4 + 1];
            a2 += red[tid * 4 + 2];
            a3 += red[tid * 4 + 3];
            float* gp = Gs + gg * 128 + jj;
            gp[(4 * rg + 0) * 8] = a0;
            gp[(4 * rg + 1) * 8] = a1;
            gp[(4 * rg + 2) * 8] = a2;
            gp[(4 * rg + 3) * 8] = a3;
        }
        __syncthreads();
        if (tid < 128) {
            int r = tid >> 3, j = tid & 7;
            int n = 8 * i + j;
            int row = r * 256 + t;
            const float* xg = g_XG + (size_t)row * 4096 + n;
            float pf = Gs[0 * 128 + r * 8 + j] + xg[0];
            float pi = Gs[1 * 128 + r * 8 + j] + xg[1024];
            float pc = Gs[2 * 128 + r * 8 + j] + xg[2048];
            float po = Gs[3 * 128 + r * 8 + j] + xg[3072];
            float f = 1.f / (1.f + expf(-pf));
            float ig = 1.f / (1.f + expf(-pi));
            float cd = tanhf(pc);
            float o = 1.f / (1.f + expf(-po));
            float c = f * csm[tid] + ig * cd;
            csm[tid] = c;
            float h = o * tanhf(c);
            g_Hbuf[n * 16 + r] = h;
            size_t hidx = (size_t)row * 1024 + n;
            bf16 hh = __float2bfloat16(h);
            g_HShi[hidx] = hh;
            g_HSlo[hidx] = __float2bfloat16(h - __bfloat162float(hh));
        }
        // fence-free grid barrier (cooperative-groups protocol):
        // bar.sync -> tid0 red.release.gpu -> spin ld.acquire.gpu -> bar.sync
        if (t < 255) {
            __syncthreads();
            if (tid == 0) {
                unsigned* ctr = &g_ctr[t];
                asm volatile("red.release.gpu.global.add.u32 [%0], %1;" ::"l"(ctr), "r"(1u)
                             : "memory");
                unsigned v;
                do {
                    asm volatile("ld.acquire.gpu.global.u32 %0, [%1];" : "=r"(v) : "l"(ctr)
                                 : "memory");
                } while (v < (unsigned)NB);
            }
            __syncthreads();
        }
    }
}

// ---------------- launch ----------------
extern "C" void kernel_launch(void* const* d_in, const int* in_sizes, int n_in, void* d_out,
                              int out_size) {
    const int* tokens = (const int*)d_in[0];
    const float* emb = (const float*)d_in[1];
    const float* w_f = (const float*)d_in[2];
    const float* u_f = (const float*)d_in[3];
    const float* b_f = (const float*)d_in[4];
    const float* w_i = (const float*)d_in[5];
    const float* u_i = (const float*)d_in[6];
    const float* b_i = (const float*)d_in[7];
    const float* w_c = (const float*)d_in[8];
    const float* u_c = (const float*)d_in[9];
    const float* b_c = (const float*)d_in[10];
    const float* w_o = (const float*)d_in[11];
    const float* u_o = (const float*)d_in[12];
    const float* b_o = (const float*)d_in[13];
    const float* w_out = (const float*)d_in[14];
    const float* b_out = (const float*)d_in[15];
    float* out = (float*)d_out;

    const int recur_smem_bytes = (32768 + 16384 + 512 + 512 + 128) * 4;  // 201216
    cudaFuncSetAttribute(recur_kernel, cudaFuncAttributeMaxDynamicSharedMemorySize,
                         recur_smem_bytes);

    void *p_xhi, *p_xlo, *p_wch, *p_wcl, *p_bcat, *p_xg, *p_hshi, *p_hslo, *p_woh, *p_wol;
    cudaGetSymbolAddress(&p_xhi, g_Xhi);
    cudaGetSymbolAddress(&p_xlo, g_Xlo);
    cudaGetSymbolAddress(&p_wch, g_WcatT_hi);
    cudaGetSymbolAddress(&p_wcl, g_WcatT_lo);
    cudaGetSymbolAddress(&p_bcat, g_bcat);
    cudaGetSymbolAddress(&p_xg, g_XG);
    cudaGetSymbolAddress(&p_hshi, g_HShi);
    cudaGetSymbolAddress(&p_hslo, g_HSlo);
    cudaGetSymbolAddress(&p_woh, g_WoutT_hi);
    cudaGetSymbolAddress(&p_wol, g_WoutT_lo);

    // idx 0,1: prep (2 kernels so the XG GEMM is launch #3 -> ncu-profiled slot)
    prep_a_kernel<<<4096, 256>>>(tokens, emb, b_f, b_i, b_c, b_o);
    prep_b_kernel<<<4096, 256>>>(w_f, w_i, w_c, w_o, u_f, u_i, u_c, u_o);

    // idx 2: w_out transpose+split
    woutT_split_kernel<<<dim3(V_ / 32, H_ / 32), dim3(32, 8)>>>(w_out);

    // idx 3 (profiled): XG = X @ Wcat + bcat   (M=4096, N=4096, K=1024)
    gemm_split_kernel<<<dim3(4096 / 64, 4096 / 128), 256>>>(
        (const bf16*)p_xhi, (const bf16*)p_xlo, (const bf16*)p_wch, (const bf16*)p_wcl,
        (const float*)p_bcat, (float*)p_xg, R_, 4 * H_, H_);

    // idx 4: sequential LSTM recurrence (persistent, fence-free grid barrier)
    recur_kernel<<<NB, 256, recur_smem_bytes>>>();

    // idx 5: logits = HS @ w_out + b_out   (M=4096, N=32000, K=1024)
    gemm_split_kernel<<<dim3(V_ / 64, R_ / 128), 256>>>(
        (const bf16*)p_hshi, (const bf16*)p_hslo, (const bf16*)p_woh, (const bf16*)p_wol, b_out,
        out, R_, V_, H_);
}

// round 14
// speedup vs baseline: 3.1396x; 1.3210x over previous
#include <cuda_runtime.h>
#include <cuda_bf16.h>
#include <cstdint>

typedef __nv_bfloat16 bf16;

#define H_ 1024
#define V_ 32000
#define B_ 16
#define T_ 256
#define R_ 4096   // B_*T_
#define NB 128    // persistent recurrence blocks

// ---------------- static device scratch (allocations are forbidden) ----------------
__device__ bf16  g_Xhi[R_ * H_];
__device__ bf16  g_Xlo[R_ * H_];
__device__ bf16  g_WcatT_hi[4 * H_ * H_];   // [n4][k]
__device__ bf16  g_WcatT_lo[4 * H_ * H_];
__device__ float g_bcat[4 * H_];
__device__ float g_XG[(size_t)R_ * 4 * H_]; // precomputed x-gate contributions (+bias)
__device__ uint2 g_Ufrag[2097152];          // [i][hl][c][q][lane] mma B-fragments (16MB)
__device__ bf16  g_Hphi[2][16384];          // parity-buffered h hi, [buf][b*1024+n]
__device__ bf16  g_Hplo[2][16384];          // parity-buffered h lo
__device__ bf16  g_HShi[R_ * H_];
__device__ bf16  g_HSlo[R_ * H_];
__device__ bf16  g_WoutT_hi[32768000];      // V_*H_, layout [n][k]
__device__ bf16  g_WoutT_lo[32768000];
__device__ unsigned g_ctr[256];             // per-step grid-barrier counters

// ---------------- prep kernels ----------------
__global__ void prep_a_kernel(const int* __restrict__ tokens, const float* __restrict__ emb,
                              const float* __restrict__ bf_, const float* __restrict__ bi_,
                              const float* __restrict__ bc_, const float* __restrict__ bo_) {
    const int gstride = gridDim.x * blockDim.x;
    const int gtid = blockIdx.x * blockDim.x + threadIdx.x;

    if (gtid < 256) g_ctr[gtid] = 0u;
    if (gtid < 4 * H_) {
        int g = gtid >> 10, n = gtid & (H_ - 1);
        const float* b = (g == 0) ? bf_ : (g == 1) ? bi_ : (g == 2) ? bc_ : bo_;
        g_bcat[gtid] = b[n];
    }
    for (int idx = gtid; idx < R_ * H_; idx += gstride) {
        int r = idx >> 10, k = idx & (H_ - 1);
        float v = emb[(size_t)tokens[r] * H_ + k];
        bf16 h = __float2bfloat16(v);
        g_Xhi[idx] = h;
        g_Xlo[idx] = __float2bfloat16(v - __bfloat162float(h));
    }
}

__device__ __forceinline__ uint32_t pack_bf2(float a, float b) {
    __nv_bfloat162 t = __floats2bfloat162_rn(a, b);  // .x = a (low), .y = b (high)
    return *(uint32_t*)&t;
}

// prep_b: WcatT split + U mma-fragment packing.
// g_Ufrag[(((i*2 + hl)*64 + c)*4 + q)*32 + l] : B-fragment uint2 for
// block i, hi/lo=hl, k16-chunk c, n8(gate) q, lane l (g=l>>2 -> j, tg=l&3).
//   .x = (U[16c+2tg][col], U[16c+2tg+1][col])  .y = same at k+8,  col = q*1024 + 8i + g (global)
__global__ void prep_b_kernel(const float* __restrict__ wf, const float* __restrict__ wi,
                              const float* __restrict__ wc, const float* __restrict__ wo,
                              const float* __restrict__ uf, const float* __restrict__ ui,
                              const float* __restrict__ uc, const float* __restrict__ uo) {
    const int gstride = gridDim.x * blockDim.x;
    const int gtid = blockIdx.x * blockDim.x + threadIdx.x;

    for (int idx = gtid; idx < 4 * H_ * H_; idx += gstride) {
        int k = idx & 1023;
        int n4 = idx >> 10;
        int g = n4 >> 10, n = n4 & 1023;
        const float* w = (g == 0) ? wf : (g == 1) ? wi : (g == 2) ? wc : wo;
        float v = w[(size_t)k * H_ + n];
        bf16 h = __float2bfloat16(v);
        g_WcatT_hi[idx] = h;
        g_WcatT_lo[idx] = __float2bfloat16(v - __bfloat162float(h));
    }

    for (int idx = gtid; idx < 2097152; idx += gstride) {
        int l = idx & 31;
        int q = (idx >> 5) & 3;
        int c = (idx >> 7) & 63;
        int hl = (idx >> 13) & 1;
        int i = idx >> 14;
        int g = l >> 2, tg = l & 3;
        const float* u = (q == 0) ? uf : (q == 1) ? ui : (q == 2) ? uc : uo;
        int col = 8 * i + g;
        int k0 = 16 * c + 2 * tg;
        float v00 = u[(size_t)k0 * H_ + col];
        float v01 = u[(size_t)(k0 + 1) * H_ + col];
        float v10 = u[(size_t)(k0 + 8) * H_ + col];
        float v11 = u[(size_t)(k0 + 9) * H_ + col];
        if (hl) {
            v00 -= __bfloat162float(__float2bfloat16(v00));
            v01 -= __bfloat162float(__float2bfloat16(v01));
            v10 -= __bfloat162float(__float2bfloat16(v10));
            v11 -= __bfloat162float(__float2bfloat16(v11));
        }
        uint2 r;
        r.x = pack_bf2(v00, v01);
        r.y = pack_bf2(v10, v11);
        g_Ufrag[idx] = r;
    }
}

// Tiled transpose+split: WoutT[n][k] = w_out[k][n]
__global__ __launch_bounds__(256) void woutT_split_kernel(const float* __restrict__ wout) {
    __shared__ float t[32][33];
    int n0 = blockIdx.x * 32, k0 = blockIdx.y * 32;
    int tx = threadIdx.x, ty = threadIdx.y;  // 32 x 8
#pragma unroll
    for (int i = ty; i < 32; i += 8) t[i][tx] = wout[(size_t)(k0 + i) * V_ + n0 + tx];
    __syncthreads();
#pragma unroll
    for (int i = ty; i < 32; i += 8) {
        float v = t[tx][i];
        bf16 h = __float2bfloat16(v);
        size_t o = (size_t)(n0 + i) * H_ + k0 + tx;
        g_WoutT_hi[o] = h;
        g_WoutT_lo[o] = __float2bfloat16(v - __bfloat162float(h));
    }
}

// ---------------- split-bf16 GEMM (round-12 proven: 128x64 tiles, 2 blocks/SM) ----------------
__device__ __forceinline__ void mma16816(float c[4], const uint32_t a[4], uint32_t b0,
                                         uint32_t b1) {
    asm volatile(
        "mma.sync.aligned.m16n8k16.row.col.f32.bf16.bf16.f32 "
        "{%0,%1,%2,%3}, {%4,%5,%6,%7}, {%8,%9}, {%0,%1,%2,%3};\n"
        : "+f"(c[0]), "+f"(c[1]), "+f"(c[2]), "+f"(c[3])
        : "r"(a[0]), "r"(a[1]), "r"(a[2]), "r"(a[3]), "r"(b0), "r"(b1));
}

struct Stage {
    uint4 ra[2][2];
    uint4 rb[2];
};

__device__ __forceinline__ void g_load(Stage& s, const bf16* __restrict__ Ahi,
                                       const bf16* __restrict__ Alo,
                                       const bf16* __restrict__ Bhi,
                                       const bf16* __restrict__ Blo, int bm0, int bn0, int K,
                                       int k0, int tid) {
#pragma unroll
    for (int q = 0; q < 2; q++) {
        int idx = q * 256 + tid;
        int r = idx >> 2, cg = idx & 3;
        s.ra[0][q] = *(const uint4*)(Ahi + (size_t)(bm0 + r) * K + k0 + cg * 8);
        s.ra[1][q] = *(const uint4*)(Alo + (size_t)(bm0 + r) * K + k0 + cg * 8);
    }
    int r = tid >> 2, cg = tid & 3;
    s.rb[0] = *(const uint4*)(Bhi + (size_t)(bn0 + r) * K + k0 + cg * 8);
    s.rb[1] = *(const uint4*)(Blo + (size_t)(bn0 + r) * K + k0 + cg * 8);
}

__device__ __forceinline__ void g_store(const Stage& s, bf16 (*As)[128][40], bf16 (*Bs)[64][40],
                                        int tid) {
#pragma unroll
    for (int q = 0; q < 2; q++) {
        int idx = q * 256 + tid;
        int r = idx >> 2, cg = idx & 3;
        *(uint4*)&As[0][r][cg * 8] = s.ra[0][q];
        *(uint4*)&As[1][r][cg * 8] = s.ra[1][q];
    }
    int r = tid >> 2, cg = tid & 3;
    *(uint4*)&Bs[0][r][cg * 8] = s.rb[0];
    *(uint4*)&Bs[1][r][cg * 8] = s.rb[1];
}

__global__ __launch_bounds__(256, 2) void gemm_split_kernel(
    const bf16* __restrict__ Ahi, const bf16* __restrict__ Alo, const bf16* __restrict__ Bhi,
    const bf16* __restrict__ Blo, const float* __restrict__ bias, float* __restrict__ C, int M,
    int N, int K) {
    __shared__ bf16 As[2][128][40];
    __shared__ bf16 Bs[2][64][40];

    const int tid = threadIdx.x;
    const int bn0 = blockIdx.x * 64;
    const int bm0 = blockIdx.y * 128;
    const int lane = tid & 31, warp = tid >> 5;
    const int wm = warp & 3, wn = warp >> 2;
    const int g = lane >> 2, tg = lane & 3;

    float acc[2][4][4];
#pragma unroll
    for (int mi = 0; mi < 2; mi++)
#pragma unroll
        for (int nj = 0; nj < 4; nj++)
#pragma unroll
            for (int e = 0; e < 4; e++) acc[mi][nj][e] = 0.f;

    Stage st;
    g_load(st, Ahi, Alo, Bhi, Blo, bm0, bn0, K, 0, tid);
    g_store(st, As, Bs, tid);
    __syncthreads();

    const int nk = K / 32;
    for (int kt = 0; kt < nk; kt++) {
        if (kt + 1 < nk) g_load(st, Ahi, Alo, Bhi, Blo, bm0, bn0, K, (kt + 1) * 32, tid);
#pragma unroll
        for (int ks = 0; ks < 32; ks += 16) {
            uint32_t ah[2][4], al[2][4];
#pragma unroll
            for (int mi = 0; mi < 2; mi++) {
                int r0 = wm * 32 + mi * 16 + g;
                ah[mi][0] = *(const uint32_t*)&As[0][r0][ks + 2 * tg];
                ah[mi][1] = *(const uint32_t*)&As[0][r0 + 8][ks + 2 * tg];
                ah[mi][2] = *(const uint32_t*)&As[0][r0][ks + 2 * tg + 8];
                ah[mi][3] = *(const uint32_t*)&As[0][r0 + 8][ks + 2 * tg + 8];
                al[mi][0] = *(const uint32_t*)&As[1][r0][ks + 2 * tg];
                al[mi][1] = *(const uint32_t*)&As[1][r0 + 8][ks + 2 * tg];
                al[mi][2] = *(const uint32_t*)&As[1][r0][ks + 2 * tg + 8];
                al[mi][3] = *(const uint32_t*)&As[1][r0 + 8][ks + 2 * tg + 8];
            }
#pragma unroll
            for (int nj = 0; nj < 4; nj++) {
                int n = wn * 32 + nj * 8 + g;
                uint32_t bh0 = *(const uint32_t*)&Bs[0][n][ks + 2 * tg];
                uint32_t bh1 = *(const uint32_t*)&Bs[0][n][ks + 2 * tg + 8];
                uint32_t bl0 = *(const uint32_t*)&Bs[1][n][ks + 2 * tg];
                uint32_t bl1 = *(const uint32_t*)&Bs[1][n][ks + 2 * tg + 8];
#pragma unroll
                for (int mi = 0; mi < 2; mi++) {
                    mma16816(acc[mi][nj], ah[mi], bh0, bh1);
                    mma16816(acc[mi][nj], ah[mi], bl0, bl1);
                    mma16816(acc[mi][nj], al[mi], bh0, bh1);
                }
            }
        }
        __syncthreads();
        if (kt + 1 < nk) {
            g_store(st, As, Bs, tid);
            __syncthreads();
        }
    }

#pragma unroll
    for (int mi = 0; mi < 2; mi++) {
#pragma unroll
        for (int nj = 0; nj < 4; nj++) {
            int r = bm0 + wm * 32 + mi * 16 + g;
            int nc = bn0 + wn * 32 + nj * 8 + 2 * tg;
            float b0 = bias[nc], b1 = bias[nc + 1];
            float2 v0 = make_float2(acc[mi][nj][0] + b0, acc[mi][nj][1] + b1);
            float2 v1 = make_float2(acc[mi][nj][2] + b0, acc[mi][nj][3] + b1);
            *(float2*)&C[(size_t)r * N + nc] = v0;
            *(float2*)&C[(size_t)(r + 8) * N + nc] = v1;
        }
    }
}

// ---------------- persistent LSTM recurrence: mma.sync h@U ----------------
// 128 blocks x 256 threads (8 warps). Block i owns hidden cols 8i..8i+7 (all 4 gates,
// n_local = 8q+g -> gate q, j=g). Warp w covers k16-chunks c = 8w..8w+7 (k=1024).
// Per step: C[16b x 32n] = h[16x1024] @ U[1024x32] via split-bf16 3-pass mma, fp32 acc;
// cross-warp k-reduction in smem; gate math; h written bf16 hi/lo to parity buffer.
// SMEM: U frags 128KB (resident) + partials 16KB + csm. h read via __ldcg (L1-safe).

#define RSM_U_U2 16384                       // uint2 count of U frag slice
#define RSM_PC_OFF (RSM_U_U2 * 8)            // bytes: 131072
#define RSM_CS_OFF (RSM_PC_OFF + 8 * 16 * 32 * 4)  // +16384 = 147456
#define RSM_TOTAL (RSM_CS_OFF + 512)         // 147968

extern __shared__ char recur_smem_raw[];

__global__ __launch_bounds__(256) void recur_kernel() {
    uint2* sU = (uint2*)recur_smem_raw;
    float* pC = (float*)(recur_smem_raw + RSM_PC_OFF);  // [w][b][n] = w*512 + b*32 + n
    float* csm = (float*)(recur_smem_raw + RSM_CS_OFF);

    const int i = blockIdx.x;
    const int tid = threadIdx.x;
    const int w = tid >> 5;
    const int l = tid & 31;
    const int g = l >> 2, tg = l & 3;

    // stage this block's U fragment slice (131072 B)
    {
        const float4* src = (const float4*)(g_Ufrag + (size_t)i * RSM_U_U2);
        float4* dst = (float4*)sU;
#pragma unroll
        for (int q = 0; q < 32; q++) dst[tid + q * 256] = src[tid + q * 256];
    }
    if (tid < 128) csm[tid] = 0.f;
    __syncthreads();

    // per-lane A-fragment element offsets into Hp (bf16 elements)
    const int a_off = g * 1024 + 2 * tg;  // + 16c (+8 for k-high), +8192 for b=g+8

    for (int t = 0; t < 256; t++) {
        float acc[4][4];
#pragma unroll
        for (int q = 0; q < 4; q++)
#pragma unroll
            for (int e = 0; e < 4; e++) acc[q][e] = 0.f;

        if (t > 0) {
            const int rp = (t - 1) & 1;
            const unsigned* Hhi = (const unsigned*)g_Hphi[rp];
            const unsigned* Hlo = (const unsigned*)g_Hplo[rp];
            // preload all 8 chunks' A fragments (L2-only loads; MLP=64)
            uint32_t ahf[8][4], alf[8][4];
#pragma unroll
            for (int cc = 0; cc < 8; cc++) {
                int c = w * 8 + cc;
                int e0 = (a_off + 16 * c) >> 1;  // unsigned index (2 bf16 per u32)
                ahf[cc][0] = __ldcg(Hhi + e0);
                ahf[cc][1] = __ldcg(Hhi + e0 + 4096);
                ahf[cc][2] = __ldcg(Hhi + e0 + 4);
                ahf[cc][3] = __ldcg(Hhi + e0 + 4100);
                alf[cc][0] = __ldcg(Hlo + e0);
                alf[cc][1] = __ldcg(Hlo + e0 + 4096);
                alf[cc][2] = __ldcg(Hlo + e0 + 4);
                alf[cc][3] = __ldcg(Hlo + e0 + 4100);
            }
#pragma unroll
            for (int cc = 0; cc < 8; cc++) {
                int c = w * 8 + cc;
#pragma unroll
                for (int q = 0; q < 4; q++) {
                    uint2 bh = sU[(c * 4 + q) * 32 + l];
                    uint2 bl = sU[((64 + c) * 4 + q) * 32 + l];
                    mma16816(acc[q], ahf[cc], bh.x, bh.y);
                    mma16816(acc[q], ahf[cc], bl.x, bl.y);
                    mma16816(acc[q], alf[cc], bh.x, bh.y);
                }
            }
        }

        // store per-warp partials: c0..c3 -> (b,n) per mma C-fragment layout
        {
            float* base = pC + w * 512;
#pragma unroll
            for (int q = 0; q < 4; q++) {
                int n = 8 * q + 2 * tg;
                base[g * 32 + n] = acc[q][0];
                base[g * 32 + n + 1] = acc[q][1];
                base[(g + 8) * 32 + n] = acc[q][2];
                base[(g + 8) * 32 + n + 1] = acc[q][3];
            }
        }
        __syncthreads();

        if (tid < 128) {
            int b = tid >> 3, j = tid & 7;
            float s0 = 0.f, s1 = 0.f, s2 = 0.f, s3 = 0.f;
#pragma unroll
            for (int ww = 0; ww < 8; ww++) {
                const float* p = pC + ww * 512 + b * 32 + j;
                s0 += p[0];
                s1 += p[8];
                s2 += p[16];
                s3 += p[24];
            }
            int n = 8 * i + j;
            int row = b * 256 + t;
            const float* xg = g_XG + (size_t)row * 4096 + n;
            float pf = s0 + xg[0];
            float pi = s1 + xg[1024];
            float pc = s2 + xg[2048];
            float po = s3 + xg[3072];
            float f = 1.f / (1.f + expf(-pf));
            float ig = 1.f / (1.f + expf(-pi));
            float cd = tanhf(pc);
            float o = 1.f / (1.f + expf(-po));
            float c = f * csm[tid] + ig * cd;
            csm[tid] = c;
            float h = o * tanhf(c);
            bf16 hh = __float2bfloat16(h);
            bf16 hl2 = __float2bfloat16(h - __bfloat162float(hh));
            int wp = t & 1;
            g_Hphi[wp][b * 1024 + n] = hh;
            g_Hplo[wp][b * 1024 + n] = hl2;
            size_t hidx = (size_t)row * 1024 + n;
            g_HShi[hidx] = hh;
            g_HSlo[hidx] = hl2;
        }

        if (t < 255) {
            __syncthreads();
            if (tid == 0) {
                unsigned* ctr = &g_ctr[t];
                asm volatile("red.release.gpu.global.add.u32 [%0], %1;" ::"l"(ctr), "r"(1u)
                             : "memory");
                unsigned v;
                do {
                    asm volatile("ld.acquire.gpu.global.u32 %0, [%1];" : "=r"(v) : "l"(ctr)
                                 : "memory");
                } while (v < (unsigned)NB);
            }
            __syncthreads();
        }
    }
}

// ---------------- launch ----------------
extern "C" void kernel_launch(void* const* d_in, const int* in_sizes, int n_in, void* d_out,
                              int out_size) {
    const int* tokens = (const int*)d_in[0];
    const float* emb = (const float*)d_in[1];
    const float* w_f = (const float*)d_in[2];
    const float* u_f = (const float*)d_in[3];
    const float* b_f = (const float*)d_in[4];
    const float* w_i = (const float*)d_in[5];
    const float* u_i = (const float*)d_in[6];
    const float* b_i = (const float*)d_in[7];
    const float* w_c = (const float*)d_in[8];
    const float* u_c = (const float*)d_in[9];
    const float* b_c = (const float*)d_in[10];
    const float* w_o = (const float*)d_in[11];
    const float* u_o = (const float*)d_in[12];
    const float* b_o = (const float*)d_in[13];
    const float* w_out = (const float*)d_in[14];
    const float* b_out = (const float*)d_in[15];
    float* out = (float*)d_out;

    cudaFuncSetAttribute(recur_kernel, cudaFuncAttributeMaxDynamicSharedMemorySize, RSM_TOTAL);

    void *p_xhi, *p_xlo, *p_wch, *p_wcl, *p_bcat, *p_xg, *p_hshi, *p_hslo, *p_woh, *p_wol;
    cudaGetSymbolAddress(&p_xhi, g_Xhi);
    cudaGetSymbolAddress(&p_xlo, g_Xlo);
    cudaGetSymbolAddress(&p_wch, g_WcatT_hi);
    cudaGetSymbolAddress(&p_wcl, g_WcatT_lo);
    cudaGetSymbolAddress(&p_bcat, g_bcat);
    cudaGetSymbolAddress(&p_xg, g_XG);
    cudaGetSymbolAddress(&p_hshi, g_HShi);
    cudaGetSymbolAddress(&p_hslo, g_HSlo);
    cudaGetSymbolAddress(&p_woh, g_WoutT_hi);
    cudaGetSymbolAddress(&p_wol, g_WoutT_lo);

    // idx 0,1: prep
    prep_a_kernel<<<4096, 256>>>(tokens, emb, b_f, b_i, b_c, b_o);
    prep_b_kernel<<<4096, 256>>>(w_f, w_i, w_c, w_o, u_f, u_i, u_c, u_o);

    // idx 2: w_out transpose+split
    woutT_split_kernel<<<dim3(V_ / 32, H_ / 32), dim3(32, 8)>>>(w_out);

    // idx 3 (profiled): XG = X @ Wcat + bcat   (M=4096, N=4096, K=1024)
    gemm_split_kernel<<<dim3(4096 / 64, 4096 / 128), 256>>>(
        (const bf16*)p_xhi, (const bf16*)p_xlo, (const bf16*)p_wch, (const bf16*)p_wcl,
        (const float*)p_bcat, (float*)p_xg, R_, 4 * H_, H_);

    // idx 4: sequential LSTM recurrence (persistent, mma-based)
    recur_kernel<<<NB, 256, RSM_TOTAL>>>();

    // idx 5: logits = HS @ w_out + b_out   (M=4096, N=32000, K=1024)
    gemm_split_kernel<<<dim3(V_ / 64, R_ / 128), 256>>>(
        (const bf16*)p_hshi, (const bf16*)p_hslo, (const bf16*)p_woh, (const bf16*)p_wol, b_out,
        out, R_, V_, H_);
}

// round 15
// speedup vs baseline: 3.5563x; 1.1327x over previous
#include <cuda_runtime.h>
#include <cuda_bf16.h>
#include <cuda_fp16.h>
#include <cstdint>

typedef __nv_bfloat16 bf16;

#define H_ 1024
#define V_ 32000
#define B_ 16
#define T_ 256
#define R_ 4096   // B_*T_
#define NB 128    // persistent recurrence blocks

// ---------------- static device scratch (allocations are forbidden) ----------------
__device__ bf16   g_Xhi[R_ * H_];
__device__ bf16   g_Xlo[R_ * H_];
__device__ bf16   g_WcatT_hi[4 * H_ * H_];   // [n4][k]
__device__ bf16   g_WcatT_lo[4 * H_ * H_];
__device__ float  g_bcat[4 * H_];
__device__ float  g_XG[(size_t)R_ * 4 * H_]; // precomputed x-gate contributions (+bias)
__device__ uint2  g_Ufrag[2097152];          // [i][hl][c][q][lane] mma B-fragments (16MB)
__device__ bf16   g_Hphi[2][16384];          // parity-buffered h hi (recurrence mma A)
__device__ bf16   g_Hplo[2][16384];          // parity-buffered h lo
__device__ __half g_HShi[R_ * H_];           // h history, fp16 hi (out-GEMM A)
__device__ __half g_HSlo[R_ * H_];           // h history, fp16 lo
__device__ __half g_WoutT_h[32768000];       // V_*H_, layout [n][k], single fp16
__device__ unsigned g_ctr[256];              // per-step grid-barrier counters

// ---------------- prep kernels ----------------
__global__ void prep_a_kernel(const int* __restrict__ tokens, const float* __restrict__ emb,
                              const float* __restrict__ bf_, const float* __restrict__ bi_,
                              const float* __restrict__ bc_, const float* __restrict__ bo_) {
    const int gstride = gridDim.x * blockDim.x;
    const int gtid = blockIdx.x * blockDim.x + threadIdx.x;

    if (gtid < 256) g_ctr[gtid] = 0u;
    if (gtid < 4 * H_) {
        int g = gtid >> 10, n = gtid & (H_ - 1);
        const float* b = (g == 0) ? bf_ : (g == 1) ? bi_ : (g == 2) ? bc_ : bo_;
        g_bcat[gtid] = b[n];
    }
    for (int idx = gtid; idx < R_ * H_; idx += gstride) {
        int r = idx >> 10, k = idx & (H_ - 1);
        float v = emb[(size_t)tokens[r] * H_ + k];
        bf16 h = __float2bfloat16(v);
        g_Xhi[idx] = h;
        g_Xlo[idx] = __float2bfloat16(v - __bfloat162float(h));
    }
}

__device__ __forceinline__ uint32_t pack_bf2(float a, float b) {
    __nv_bfloat162 t = __floats2bfloat162_rn(a, b);
    return *(uint32_t*)&t;
}

// prep_b: WcatT split + U mma-fragment packing (unchanged from R14).
__global__ void prep_b_kernel(const float* __restrict__ wf, const float* __restrict__ wi,
                              const float* __restrict__ wc, const float* __restrict__ wo,
                              const float* __restrict__ uf, const float* __restrict__ ui,
                              const float* __restrict__ uc, const float* __restrict__ uo) {
    const int gstride = gridDim.x * blockDim.x;
    const int gtid = blockIdx.x * blockDim.x + threadIdx.x;

    for (int idx = gtid; idx < 4 * H_ * H_; idx += gstride) {
        int k = idx & 1023;
        int n4 = idx >> 10;
        int g = n4 >> 10, n = n4 & 1023;
        const float* w = (g == 0) ? wf : (g == 1) ? wi : (g == 2) ? wc : wo;
        float v = w[(size_t)k * H_ + n];
        bf16 h = __float2bfloat16(v);
        g_WcatT_hi[idx] = h;
        g_WcatT_lo[idx] = __float2bfloat16(v - __bfloat162float(h));
    }

    for (int idx = gtid; idx < 2097152; idx += gstride) {
        int l = idx & 31;
        int q = (idx >> 5) & 3;
        int c = (idx >> 7) & 63;
        int hl = (idx >> 13) & 1;
        int i = idx >> 14;
        int g = l >> 2, tg = l & 3;
        const float* u = (q == 0) ? uf : (q == 1) ? ui : (q == 2) ? uc : uo;
        int col = 8 * i + g;
        int k0 = 16 * c + 2 * tg;
        float v00 = u[(size_t)k0 * H_ + col];
        float v01 = u[(size_t)(k0 + 1) * H_ + col];
        float v10 = u[(size_t)(k0 + 8) * H_ + col];
        float v11 = u[(size_t)(k0 + 9) * H_ + col];
        if (hl) {
            v00 -= __bfloat162float(__float2bfloat16(v00));
            v01 -= __bfloat162float(__float2bfloat16(v01));
            v10 -= __bfloat162float(__float2bfloat16(v10));
            v11 -= __bfloat162float(__float2bfloat16(v11));
        }
        uint2 r;
        r.x = pack_bf2(v00, v01);
        r.y = pack_bf2(v10, v11);
        g_Ufrag[idx] = r;
    }
}

// Tiled transpose: WoutT[n][k] = w_out[k][n], single fp16.
__global__ __launch_bounds__(256) void woutT_split_kernel(const float* __restrict__ wout) {
    __shared__ float t[32][33];
    int n0 = blockIdx.x * 32, k0 = blockIdx.y * 32;
    int tx = threadIdx.x, ty = threadIdx.y;  // 32 x 8
#pragma unroll
    for (int i = ty; i < 32; i += 8) t[i][tx] = wout[(size_t)(k0 + i) * V_ + n0 + tx];
    __syncthreads();
#pragma unroll
    for (int i = ty; i < 32; i += 8) {
        size_t o = (size_t)(n0 + i) * H_ + k0 + tx;
        g_WoutT_h[o] = __float2half(t[tx][i]);
    }
}

// ---------------- split-bf16 GEMM (R12 proven; used for XG only) ----------------
__device__ __forceinline__ void mma16816(float c[4], const uint32_t a[4], uint32_t b0,
                                         uint32_t b1) {
    asm volatile(
        "mma.sync.aligned.m16n8k16.row.col.f32.bf16.bf16.f32 "
        "{%0,%1,%2,%3}, {%4,%5,%6,%7}, {%8,%9}, {%0,%1,%2,%3};\n"
        : "+f"(c[0]), "+f"(c[1]), "+f"(c[2]), "+f"(c[3])
        : "r"(a[0]), "r"(a[1]), "r"(a[2]), "r"(a[3]), "r"(b0), "r"(b1));
}

__device__ __forceinline__ void mma16816h(float c[4], const uint32_t a[4], uint32_t b0,
                                          uint32_t b1) {
    asm volatile(
        "mma.sync.aligned.m16n8k16.row.col.f32.f16.f16.f32 "
        "{%0,%1,%2,%3}, {%4,%5,%6,%7}, {%8,%9}, {%0,%1,%2,%3};\n"
        : "+f"(c[0]), "+f"(c[1]), "+f"(c[2]), "+f"(c[3])
        : "r"(a[0]), "r"(a[1]), "r"(a[2]), "r"(a[3]), "r"(b0), "r"(b1));
}

struct Stage {
    uint4 ra[2][2];
    uint4 rb[2];
};

__device__ __forceinline__ void g_load(Stage& s, const bf16* __restrict__ Ahi,
                                       const bf16* __restrict__ Alo,
                                       const bf16* __restrict__ Bhi,
                                       const bf16* __restrict__ Blo, int bm0, int bn0, int K,
                                       int k0, int tid) {
#pragma unroll
    for (int q = 0; q < 2; q++) {
        int idx = q * 256 + tid;
        int r = idx >> 2, cg = idx & 3;
        s.ra[0][q] = *(const uint4*)(Ahi + (size_t)(bm0 + r) * K + k0 + cg * 8);
        s.ra[1][q] = *(const uint4*)(Alo + (size_t)(bm0 + r) * K + k0 + cg * 8);
    }
    int r = tid >> 2, cg = tid & 3;
    s.rb[0] = *(const uint4*)(Bhi + (size_t)(bn0 + r) * K + k0 + cg * 8);
    s.rb[1] = *(const uint4*)(Blo + (size_t)(bn0 + r) * K + k0 + cg * 8);
}

__device__ __forceinline__ void g_store(const Stage& s, bf16 (*As)[128][40], bf16 (*Bs)[64][40],
                                        int tid) {
#pragma unroll
    for (int q = 0; q < 2; q++) {
        int idx = q * 256 + tid;
        int r = idx >> 2, cg = idx & 3;
        *(uint4*)&As[0][r][cg * 8] = s.ra[0][q];
        *(uint4*)&As[1][r][cg * 8] = s.ra[1][q];
    }
    int r = tid >> 2, cg = tid & 3;
    *(uint4*)&Bs[0][r][cg * 8] = s.rb[0];
    *(uint4*)&Bs[1][r][cg * 8] = s.rb[1];
}

__global__ __launch_bounds__(256, 2) void gemm_split_kernel(
    const bf16* __restrict__ Ahi, const bf16* __restrict__ Alo, const bf16* __restrict__ Bhi,
    const bf16* __restrict__ Blo, const float* __restrict__ bias, float* __restrict__ C, int M,
    int N, int K) {
    __shared__ bf16 As[2][128][40];
    __shared__ bf16 Bs[2][64][40];

    const int tid = threadIdx.x;
    const int bn0 = blockIdx.x * 64;
    const int bm0 = blockIdx.y * 128;
    const int lane = tid & 31, warp = tid >> 5;
    const int wm = warp & 3, wn = warp >> 2;
    const int g = lane >> 2, tg = lane & 3;

    float acc[2][4][4];
#pragma unroll
    for (int mi = 0; mi < 2; mi++)
#pragma unroll
        for (int nj = 0; nj < 4; nj++)
#pragma unroll
            for (int e = 0; e < 4; e++) acc[mi][nj][e] = 0.f;

    Stage st;
    g_load(st, Ahi, Alo, Bhi, Blo, bm0, bn0, K, 0, tid);
    g_store(st, As, Bs, tid);
    __syncthreads();

    const int nk = K / 32;
    for (int kt = 0; kt < nk; kt++) {
        if (kt + 1 < nk) g_load(st, Ahi, Alo, Bhi, Blo, bm0, bn0, K, (kt + 1) * 32, tid);
#pragma unroll
        for (int ks = 0; ks < 32; ks += 16) {
            uint32_t ah[2][4], al[2][4];
#pragma unroll
            for (int mi = 0; mi < 2; mi++) {
                int r0 = wm * 32 + mi * 16 + g;
                ah[mi][0] = *(const uint32_t*)&As[0][r0][ks + 2 * tg];
                ah[mi][1] = *(const uint32_t*)&As[0][r0 + 8][ks + 2 * tg];
                ah[mi][2] = *(const uint32_t*)&As[0][r0][ks + 2 * tg + 8];
                ah[mi][3] = *(const uint32_t*)&As[0][r0 + 8][ks + 2 * tg + 8];
                al[mi][0] = *(const uint32_t*)&As[1][r0][ks + 2 * tg];
                al[mi][1] = *(const uint32_t*)&As[1][r0 + 8][ks + 2 * tg];
                al[mi][2] = *(const uint32_t*)&As[1][r0][ks + 2 * tg + 8];
                al[mi][3] = *(const uint32_t*)&As[1][r0 + 8][ks + 2 * tg + 8];
            }
#pragma unroll
            for (int nj = 0; nj < 4; nj++) {
                int n = wn * 32 + nj * 8 + g;
                uint32_t bh0 = *(const uint32_t*)&Bs[0][n][ks + 2 * tg];
                uint32_t bh1 = *(const uint32_t*)&Bs[0][n][ks + 2 * tg + 8];
                uint32_t bl0 = *(const uint32_t*)&Bs[1][n][ks + 2 * tg];
                uint32_t bl1 = *(const uint32_t*)&Bs[1][n][ks + 2 * tg + 8];
#pragma unroll
                for (int mi = 0; mi < 2; mi++) {
                    mma16816(acc[mi][nj], ah[mi], bh0, bh1);
                    mma16816(acc[mi][nj], ah[mi], bl0, bl1);
                    mma16816(acc[mi][nj], al[mi], bh0, bh1);
                }
            }
        }
        __syncthreads();
        if (kt + 1 < nk) {
            g_store(st, As, Bs, tid);
            __syncthreads();
        }
    }

#pragma unroll
    for (int mi = 0; mi < 2; mi++) {
#pragma unroll
        for (int nj = 0; nj < 4; nj++) {
            int r = bm0 + wm * 32 + mi * 16 + g;
            int nc = bn0 + wn * 32 + nj * 8 + 2 * tg;
            float b0 = bias[nc], b1 = bias[nc + 1];
            float2 v0 = make_float2(acc[mi][nj][0] + b0, acc[mi][nj][1] + b1);
            float2 v1 = make_float2(acc[mi][nj][2] + b0, acc[mi][nj][3] + b1);
            *(float2*)&C[(size_t)r * N + nc] = v0;
            *(float2*)&C[(size_t)(r + 8) * N + nc] = v1;
        }
    }
}

// ---------------- fp16 2-pass GEMM (output projection): C = (Ah+Al) @ B^T + bias ----------------
// A fp16 hi/lo [M][K], B single fp16 [N][K]. 128x64 tiles, BK=32, 2 blocks/SM.
// L2 panel swizzle: 4 m-tiles per panel sweep all n-tiles.
struct StageH {
    uint4 ra[2][2];
    uint4 rb;
};

__global__ __launch_bounds__(256, 2) void gemm_half_kernel(
    const __half* __restrict__ Ahi, const __half* __restrict__ Alo,
    const __half* __restrict__ B, const float* __restrict__ bias, float* __restrict__ C, int M,
    int N, int K) {
    __shared__ __half As[2][128][40];
    __shared__ __half Bs[64][40];

    const int tid = threadIdx.x;
    const int lane = tid & 31, warp = tid >> 5;
    const int wm = warp & 3, wn = warp >> 2;
    const int g = lane >> 2, tg = lane & 3;

    const int nt = N >> 6;
    int bid = blockIdx.x;
    int panel = bid / (4 * nt);
    int ii = bid - panel * 4 * nt;
    const int bm0 = (panel * 4 + (ii & 3)) << 7;
    const int bn0 = (ii >> 2) << 6;

    float acc[2][4][4];
#pragma unroll
    for (int mi = 0; mi < 2; mi++)
#pragma unroll
        for (int nj = 0; nj < 4; nj++)
#pragma unroll
            for (int e = 0; e < 4; e++) acc[mi][nj][e] = 0.f;

    StageH st;
    auto ld = [&](int k0) {
#pragma unroll
        for (int q = 0; q < 2; q++) {
            int idx = q * 256 + tid;
            int r = idx >> 2, cg = idx & 3;
            st.ra[0][q] = *(const uint4*)(Ahi + (size_t)(bm0 + r) * K + k0 + cg * 8);
            st.ra[1][q] = *(const uint4*)(Alo + (size_t)(bm0 + r) * K + k0 + cg * 8);
        }
        int r = tid >> 2, cg = tid & 3;
        st.rb = *(const uint4*)(B + (size_t)(bn0 + r) * K + k0 + cg * 8);
    };
    auto stg = [&]() {
#pragma unroll
        for (int q = 0; q < 2; q++) {
            int idx = q * 256 + tid;
            int r = idx >> 2, cg = idx & 3;
            *(uint4*)&As[0][r][cg * 8] = st.ra[0][q];
            *(uint4*)&As[1][r][cg * 8] = st.ra[1][q];
        }
        int r = tid >> 2, cg = tid & 3;
        *(uint4*)&Bs[r][cg * 8] = st.rb;
    };

    ld(0);
    stg();
    __syncthreads();

    const int nk = K / 32;
    for (int kt = 0; kt < nk; kt++) {
        if (kt + 1 < nk) ld((kt + 1) * 32);
#pragma unroll
        for (int ks = 0; ks < 32; ks += 16) {
            uint32_t ah[2][4], al[2][4];
#pragma unroll
            for (int mi = 0; mi < 2; mi++) {
                int r0 = wm * 32 + mi * 16 + g;
                ah[mi][0] = *(const uint32_t*)&As[0][r0][ks + 2 * tg];
                ah[mi][1] = *(const uint32_t*)&As[0][r0 + 8][ks + 2 * tg];
                ah[mi][2] = *(const uint32_t*)&As[0][r0][ks + 2 * tg + 8];
                ah[mi][3] = *(const uint32_t*)&As[0][r0 + 8][ks + 2 * tg + 8];
                al[mi][0] = *(const uint32_t*)&As[1][r0][ks + 2 * tg];
                al[mi][1] = *(const uint32_t*)&As[1][r0 + 8][ks + 2 * tg];
                al[mi][2] = *(const uint32_t*)&As[1][r0][ks + 2 * tg + 8];
                al[mi][3] = *(const uint32_t*)&As[1][r0 + 8][ks + 2 * tg + 8];
            }
#pragma unroll
            for (int nj = 0; nj < 4; nj++) {
                int n = wn * 32 + nj * 8 + g;
                uint32_t b0 = *(const uint32_t*)&Bs[n][ks + 2 * tg];
                uint32_t b1 = *(const uint32_t*)&Bs[n][ks + 2 * tg + 8];
#pragma unroll
                for (int mi = 0; mi < 2; mi++) {
                    mma16816h(acc[mi][nj], ah[mi], b0, b1);
                    mma16816h(acc[mi][nj], al[mi], b0, b1);
                }
            }
        }
        __syncthreads();
        if (kt + 1 < nk) {
            stg();
            __syncthreads();
        }
    }

#pragma unroll
    for (int mi = 0; mi < 2; mi++) {
#pragma unroll
        for (int nj = 0; nj < 4; nj++) {
            int r = bm0 + wm * 32 + mi * 16 + g;
            int nc = bn0 + wn * 32 + nj * 8 + 2 * tg;
            float b0 = bias[nc], b1 = bias[nc + 1];
            float2 v0 = make_float2(acc[mi][nj][0] + b0, acc[mi][nj][1] + b1);
            float2 v1 = make_float2(acc[mi][nj][2] + b0, acc[mi][nj][3] + b1);
            *(float2*)&C[(size_t)r * N + nc] = v0;
            *(float2*)&C[(size_t)(r + 8) * N + nc] = v1;
        }
    }
}

// ---------------- persistent LSTM recurrence: mma.sync h@U (R14 proven) ----------------
#define RSM_U_U2 16384
#define RSM_PC_OFF (RSM_U_U2 * 8)
#define RSM_CS_OFF (RSM_PC_OFF + 8 * 16 * 32 * 4)
#define RSM_TOTAL (RSM_CS_OFF + 512)

extern __shared__ char recur_smem_raw[];

__global__ __launch_bounds__(256) void recur_kernel() {
    uint2* sU = (uint2*)recur_smem_raw;
    float* pC = (float*)(recur_smem_raw + RSM_PC_OFF);
    float* csm = (float*)(recur_smem_raw + RSM_CS_OFF);

    const int i = blockIdx.x;
    const int tid = threadIdx.x;
    const int w = tid >> 5;
    const int l = tid & 31;
    const int g = l >> 2, tg = l & 3;

    {
        const float4* src = (const float4*)(g_Ufrag + (size_t)i * RSM_U_U2);
        float4* dst = (float4*)sU;
#pragma unroll
        for (int q = 0; q < 32; q++) dst[tid + q * 256] = src[tid + q * 256];
    }
    if (tid < 128) csm[tid] = 0.f;
    __syncthreads();

    const int a_off = g * 1024 + 2 * tg;

    for (int t = 0; t < 256; t++) {
        float acc[4][4];
#pragma unroll
        for (int q = 0; q < 4; q++)
#pragma unroll
            for (int e = 0; e < 4; e++) acc[q][e] = 0.f;

        if (t > 0) {
            const int rp = (t - 1) & 1;
            const unsigned* Hhi = (const unsigned*)g_Hphi[rp];
            const unsigned* Hlo = (const unsigned*)g_Hplo[rp];
            uint32_t ahf[8][4], alf[8][4];
#pragma unroll
            for (int cc = 0; cc < 8; cc++) {
                int c = w * 8 + cc;
                int e0 = (a_off + 16 * c) >> 1;
                ahf[cc][0] = __ldcg(Hhi + e0);
                ahf[cc][1] = __ldcg(Hhi + e0 + 4096);
                ahf[cc][2] = __ldcg(Hhi + e0 + 4);
                ahf[cc][3] = __ldcg(Hhi + e0 + 4100);
                alf[cc][0] = __ldcg(Hlo + e0);
                alf[cc][1] = __ldcg(Hlo + e0 + 4096);
                alf[cc][2] = __ldcg(Hlo + e0 + 4);
                alf[cc][3] = __ldcg(Hlo + e0 + 4100);
            }
#pragma unroll
            for (int cc = 0; cc < 8; cc++) {
                int c = w * 8 + cc;
#pragma unroll
                for (int q = 0; q < 4; q++) {
                    uint2 bh = sU[(c * 4 + q) * 32 + l];
                    uint2 bl = sU[((64 + c) * 4 + q) * 32 + l];
                    mma16816(acc[q], ahf[cc], bh.x, bh.y);
                    mma16816(acc[q], ahf[cc], bl.x, bl.y);
                    mma16816(acc[q], alf[cc], bh.x, bh.y);
                }
            }
        }

        {
            float* base = pC + w * 512;
#pragma unroll
            for (int q = 0; q < 4; q++) {
                int n = 8 * q + 2 * tg;
                base[g * 32 + n] = acc[q][0];
                base[g * 32 + n + 1] = acc[q][1];
                base[(g + 8) * 32 + n] = acc[q][2];
                base[(g + 8) * 32 + n + 1] = acc[q][3];
            }
        }
        __syncthreads();

        if (tid < 128) {
            int b = tid >> 3, j = tid & 7;
            float s0 = 0.f, s1 = 0.f, s2 = 0.f, s3 = 0.f;
#pragma unroll
            for (int ww = 0; ww < 8; ww++) {
                const float* p = pC + ww * 512 + b * 32 + j;
                s0 += p[0];
                s1 += p[8];
                s2 += p[16];
                s3 += p[24];
            }
            int n = 8 * i + j;
            int row = b * 256 + t;
            const float* xg = g_XG + (size_t)row * 4096 + n;
            float pf = s0 + xg[0];
            float pi = s1 + xg[1024];
            float pc = s2 + xg[2048];
            float po = s3 + xg[3072];
            float f = 1.f / (1.f + expf(-pf));
            float ig = 1.f / (1.f + expf(-pi));
            float cd = tanhf(pc);
            float o = 1.f / (1.f + expf(-po));
            float c = f * csm[tid] + ig * cd;
            csm[tid] = c;
            float h = o * tanhf(c);
            bf16 hh = __float2bfloat16(h);
            bf16 hl2 = __float2bfloat16(h - __bfloat162float(hh));
            int wp = t & 1;
            g_Hphi[wp][b * 1024 + n] = hh;
            g_Hplo[wp][b * 1024 + n] = hl2;
            __half fh = __float2half(h);
            __half fl = __float2half(h - __half2float(fh));
            size_t hidx = (size_t)row * 1024 + n;
            g_HShi[hidx] = fh;
            g_HSlo[hidx] = fl;
        }

        if (t < 255) {
            __syncthreads();
            if (tid == 0) {
                unsigned* ctr = &g_ctr[t];
                asm volatile("red.release.gpu.global.add.u32 [%0], %1;" ::"l"(ctr), "r"(1u)
                             : "memory");
                unsigned v;
                do {
                    asm volatile("ld.acquire.gpu.global.u32 %0, [%1];" : "=r"(v) : "l"(ctr)
                                 : "memory");
                } while (v < (unsigned)NB);
            }
            __syncthreads();
        }
    }
}

// ---------------- launch ----------------
extern "C" void kernel_launch(void* const* d_in, const int* in_sizes, int n_in, void* d_out,
                              int out_size) {
    const int* tokens = (const int*)d_in[0];
    const float* emb = (const float*)d_in[1];
    const float* w_f = (const float*)d_in[2];
    const float* u_f = (const float*)d_in[3];
    const float* b_f = (const float*)d_in[4];
    const float* w_i = (const float*)d_in[5];
    const float* u_i = (const float*)d_in[6];
    const float* b_i = (const float*)d_in[7];
    const float* w_c = (const float*)d_in[8];
    const float* u_c = (const float*)d_in[9];
    const float* b_c = (const float*)d_in[10];
    const float* w_o = (const float*)d_in[11];
    const float* u_o = (const float*)d_in[12];
    const float* b_o = (const float*)d_in[13];
    const float* w_out = (const float*)d_in[14];
    const float* b_out = (const float*)d_in[15];
    float* out = (float*)d_out;

    cudaFuncSetAttribute(recur_kernel, cudaFuncAttributeMaxDynamicSharedMemorySize, RSM_TOTAL);

    void *p_xhi, *p_xlo, *p_wch, *p_wcl, *p_bcat, *p_xg, *p_hshi, *p_hslo, *p_woh;
    cudaGetSymbolAddress(&p_xhi, g_Xhi);
    cudaGetSymbolAddress(&p_xlo, g_Xlo);
    cudaGetSymbolAddress(&p_wch, g_WcatT_hi);
    cudaGetSymbolAddress(&p_wcl, g_WcatT_lo);
    cudaGetSymbolAddress(&p_bcat, g_bcat);
    cudaGetSymbolAddress(&p_xg, g_XG);
    cudaGetSymbolAddress(&p_hshi, g_HShi);
    cudaGetSymbolAddress(&p_hslo, g_HSlo);
    cudaGetSymbolAddress(&p_woh, g_WoutT_h);

    // idx 0,1: prep
    prep_a_kernel<<<4096, 256>>>(tokens, emb, b_f, b_i, b_c, b_o);
    prep_b_kernel<<<4096, 256>>>(w_f, w_i, w_c, w_o, u_f, u_i, u_c, u_o);

    // idx 2: XG = X @ Wcat + bcat   (M=4096, N=4096, K=1024), bf16 3-pass
    gemm_split_kernel<<<dim3(4096 / 64, 4096 / 128), 256>>>(
        (const bf16*)p_xhi, (const bf16*)p_xlo, (const bf16*)p_wch, (const bf16*)p_wcl,
        (const float*)p_bcat, (float*)p_xg, R_, 4 * H_, H_);

    // idx 3 (ncu-profiled slot): sequential LSTM recurrence
    recur_kernel<<<NB, 256, RSM_TOTAL>>>();

    // idx 4: w_out transpose (single fp16)
    woutT_split_kernel<<<dim3(V_ / 32, H_ / 32), dim3(32, 8)>>>(w_out);

    // idx 5: logits = HS @ w_out + b_out  (M=4096, N=32000, K=1024), fp16 2-pass + swizzle
    gemm_half_kernel<<<(R_ / 128) * (V_ / 64), 256>>>(
        (const __half*)p_hshi, (const __half*)p_hslo, (const __half*)p_woh, b_out, out, R_, V_,
        H_);
}

// round 16
// speedup vs baseline: 4.2903x; 1.2064x over previous
#include <cuda_runtime.h>
#include <cuda_bf16.h>
#include <cuda_fp16.h>
#include <cstdint>

typedef __nv_bfloat16 bf16;

#define H_ 1024
#define V_ 32000
#define B_ 16
#define T_ 256
#define R_ 4096   // B_*T_
#define NB 128    // persistent recurrence blocks

// ---------------- static device scratch (allocations are forbidden) ----------------
__device__ bf16   g_Xhi[R_ * H_];
__device__ bf16   g_Xlo[R_ * H_];
__device__ bf16   g_WcatT_hi[4 * H_ * H_];   // [n4][k]
__device__ bf16   g_WcatT_lo[4 * H_ * H_];
__device__ float  g_bcat[4 * H_];
__device__ float  g_XG[(size_t)R_ * 4 * H_]; // precomputed x-gate contributions (+bias)
__device__ uint2  g_Ufrag[2097152];          // [i][hl][c][q][lane] mma B-fragments (16MB)
__device__ bf16   g_Hphi[2][16384];          // parity-buffered h hi (recurrence mma A)
__device__ bf16   g_Hplo[2][16384];          // parity-buffered h lo
__device__ __half g_HShi[R_ * H_];           // h history, fp16 hi (out-GEMM A)
__device__ __half g_HSlo[R_ * H_];           // h history, fp16 lo
__device__ __half g_WoutT_h[32768000];       // V_*H_, layout [n][k], single fp16
__device__ unsigned g_ctr[256];              // per-step grid-barrier counters

// ---------------- fused prep kernel (everything independent of the recurrence) ----------------
__device__ __forceinline__ uint32_t pack_bf2(float a, float b) {
    __nv_bfloat162 t = __floats2bfloat162_rn(a, b);
    return *(uint32_t*)&t;
}

__global__ __launch_bounds__(256) void prep_all_kernel(
    const int* __restrict__ tokens, const float* __restrict__ emb,
    const float* __restrict__ wf, const float* __restrict__ wi, const float* __restrict__ wc,
    const float* __restrict__ wo, const float* __restrict__ uf, const float* __restrict__ ui,
    const float* __restrict__ uc, const float* __restrict__ uo, const float* __restrict__ bf_,
    const float* __restrict__ bi_, const float* __restrict__ bc_,
    const float* __restrict__ bo_, const float* __restrict__ wout) {
    const int gstride = gridDim.x * blockDim.x;
    const int gtid = blockIdx.x * blockDim.x + threadIdx.x;
    const int tid = threadIdx.x;

    // -- section 0: tiled w_out transpose -> fp16, block-cooperative grid-stride --
    {
        __shared__ float ts[32][33];
        int tx = tid & 31, ty8 = tid >> 5;  // 32 x 8
        const int ntile = (V_ / 32) * (H_ / 32);
        for (int tile = blockIdx.x; tile < ntile; tile += gridDim.x) {
            int n0 = (tile % (V_ / 32)) * 32, k0 = (tile / (V_ / 32)) * 32;
#pragma unroll
            for (int i2 = ty8; i2 < 32; i2 += 8)
                ts[i2][tx] = wout[(size_t)(k0 + i2) * V_ + n0 + tx];
            __syncthreads();
#pragma unroll
            for (int i2 = ty8; i2 < 32; i2 += 8)
                g_WoutT_h[(size_t)(n0 + i2) * H_ + k0 + tx] = __float2half(ts[tx][i2]);
            __syncthreads();
        }
    }

    if (gtid < 256) g_ctr[gtid] = 0u;
    if (gtid < 4 * H_) {
        int g = gtid >> 10, n = gtid & (H_ - 1);
        const float* b = (g == 0) ? bf_ : (g == 1) ? bi_ : (g == 2) ? bc_ : bo_;
        g_bcat[gtid] = b[n];
    }

    // gather + split X
    for (int idx = gtid; idx < R_ * H_; idx += gstride) {
        int r = idx >> 10, k = idx & (H_ - 1);
        float v = emb[(size_t)tokens[r] * H_ + k];
        bf16 h = __float2bfloat16(v);
        g_Xhi[idx] = h;
        g_Xlo[idx] = __float2bfloat16(v - __bfloat162float(h));
    }

    // WcatT[n4][k] = w_g[k][n]
    for (int idx = gtid; idx < 4 * H_ * H_; idx += gstride) {
        int k = idx & 1023;
        int n4 = idx >> 10;
        int g = n4 >> 10, n = n4 & 1023;
        const float* w = (g == 0) ? wf : (g == 1) ? wi : (g == 2) ? wc : wo;
        float v = w[(size_t)k * H_ + n];
        bf16 h = __float2bfloat16(v);
        g_WcatT_hi[idx] = h;
        g_WcatT_lo[idx] = __float2bfloat16(v - __bfloat162float(h));
    }

    // U mma-fragment packing
    for (int idx = gtid; idx < 2097152; idx += gstride) {
        int l = idx & 31;
        int q = (idx >> 5) & 3;
        int c = (idx >> 7) & 63;
        int hl = (idx >> 13) & 1;
        int i = idx >> 14;
        int g = l >> 2, tg = l & 3;
        const float* u = (q == 0) ? uf : (q == 1) ? ui : (q == 2) ? uc : uo;
        int col = 8 * i + g;
        int k0 = 16 * c + 2 * tg;
        float v00 = u[(size_t)k0 * H_ + col];
        float v01 = u[(size_t)(k0 + 1) * H_ + col];
        float v10 = u[(size_t)(k0 + 8) * H_ + col];
        float v11 = u[(size_t)(k0 + 9) * H_ + col];
        if (hl) {
            v00 -= __bfloat162float(__float2bfloat16(v00));
            v01 -= __bfloat162float(__float2bfloat16(v01));
            v10 -= __bfloat162float(__float2bfloat16(v10));
            v11 -= __bfloat162float(__float2bfloat16(v11));
        }
        uint2 r;
        r.x = pack_bf2(v00, v01);
        r.y = pack_bf2(v10, v11);
        g_Ufrag[idx] = r;
    }
}

// ---------------- mma helpers ----------------
__device__ __forceinline__ void mma16816(float c[4], const uint32_t a[4], uint32_t b0,
                                         uint32_t b1) {
    asm volatile(
        "mma.sync.aligned.m16n8k16.row.col.f32.bf16.bf16.f32 "
        "{%0,%1,%2,%3}, {%4,%5,%6,%7}, {%8,%9}, {%0,%1,%2,%3};\n"
        : "+f"(c[0]), "+f"(c[1]), "+f"(c[2]), "+f"(c[3])
        : "r"(a[0]), "r"(a[1]), "r"(a[2]), "r"(a[3]), "r"(b0), "r"(b1));
}

__device__ __forceinline__ void mma16816h(float c[4], const uint32_t a[4], uint32_t b0,
                                          uint32_t b1) {
    asm volatile(
        "mma.sync.aligned.m16n8k16.row.col.f32.f16.f16.f32 "
        "{%0,%1,%2,%3}, {%4,%5,%6,%7}, {%8,%9}, {%0,%1,%2,%3};\n"
        : "+f"(c[0]), "+f"(c[1]), "+f"(c[2]), "+f"(c[3])
        : "r"(a[0]), "r"(a[1]), "r"(a[2]), "r"(a[3]), "r"(b0), "r"(b1));
}

__device__ __forceinline__ void cp16s(uint32_t daddr, const void* src) {
    asm volatile("cp.async.cg.shared.global [%0], [%1], 16;" ::"r"(daddr), "l"(src));
}

// ---------------- split-bf16 GEMM (R12 proven; XG only) ----------------
struct Stage {
    uint4 ra[2][2];
    uint4 rb[2];
};

__device__ __forceinline__ void g_load(Stage& s, const bf16* __restrict__ Ahi,
                                       const bf16* __restrict__ Alo,
                                       const bf16* __restrict__ Bhi,
                                       const bf16* __restrict__ Blo, int bm0, int bn0, int K,
                                       int k0, int tid) {
#pragma unroll
    for (int q = 0; q < 2; q++) {
        int idx = q * 256 + tid;
        int r = idx >> 2, cg = idx & 3;
        s.ra[0][q] = *(const uint4*)(Ahi + (size_t)(bm0 + r) * K + k0 + cg * 8);
        s.ra[1][q] = *(const uint4*)(Alo + (size_t)(bm0 + r) * K + k0 + cg * 8);
    }
    int r = tid >> 2, cg = tid & 3;
    s.rb[0] = *(const uint4*)(Bhi + (size_t)(bn0 + r) * K + k0 + cg * 8);
    s.rb[1] = *(const uint4*)(Blo + (size_t)(bn0 + r) * K + k0 + cg * 8);
}

__device__ __forceinline__ void g_store(const Stage& s, bf16 (*As)[128][40], bf16 (*Bs)[64][40],
                                        int tid) {
#pragma unroll
    for (int q = 0; q < 2; q++) {
        int idx = q * 256 + tid;
        int r = idx >> 2, cg = idx & 3;
        *(uint4*)&As[0][r][cg * 8] = s.ra[0][q];
        *(uint4*)&As[1][r][cg * 8] = s.ra[1][q];
    }
    int r = tid >> 2, cg = tid & 3;
    *(uint4*)&Bs[0][r][cg * 8] = s.rb[0];
    *(uint4*)&Bs[1][r][cg * 8] = s.rb[1];
}

__global__ __launch_bounds__(256, 2) void gemm_split_kernel(
    const bf16* __restrict__ Ahi, const bf16* __restrict__ Alo, const bf16* __restrict__ Bhi,
    const bf16* __restrict__ Blo, const float* __restrict__ bias, float* __restrict__ C, int M,
    int N, int K) {
    __shared__ bf16 As[2][128][40];
    __shared__ bf16 Bs[2][64][40];

    const int tid = threadIdx.x;
    const int bn0 = blockIdx.x * 64;
    const int bm0 = blockIdx.y * 128;
    const int lane = tid & 31, warp = tid >> 5;
    const int wm = warp & 3, wn = warp >> 2;
    const int g = lane >> 2, tg = lane & 3;

    float acc[2][4][4];
#pragma unroll
    for (int mi = 0; mi < 2; mi++)
#pragma unroll
        for (int nj = 0; nj < 4; nj++)
#pragma unroll
            for (int e = 0; e < 4; e++) acc[mi][nj][e] = 0.f;

    Stage st;
    g_load(st, Ahi, Alo, Bhi, Blo, bm0, bn0, K, 0, tid);
    g_store(st, As, Bs, tid);
    __syncthreads();

    const int nk = K / 32;
    for (int kt = 0; kt < nk; kt++) {
        if (kt + 1 < nk) g_load(st, Ahi, Alo, Bhi, Blo, bm0, bn0, K, (kt + 1) * 32, tid);
#pragma unroll
        for (int ks = 0; ks < 32; ks += 16) {
            uint32_t ah[2][4], al[2][4];
#pragma unroll
            for (int mi = 0; mi < 2; mi++) {
                int r0 = wm * 32 + mi * 16 + g;
                ah[mi][0] = *(const uint32_t*)&As[0][r0][ks + 2 * tg];
                ah[mi][1] = *(const uint32_t*)&As[0][r0 + 8][ks + 2 * tg];
                ah[mi][2] = *(const uint32_t*)&As[0][r0][ks + 2 * tg + 8];
                ah[mi][3] = *(const uint32_t*)&As[0][r0 + 8][ks + 2 * tg + 8];
                al[mi][0] = *(const uint32_t*)&As[1][r0][ks + 2 * tg];
                al[mi][1] = *(const uint32_t*)&As[1][r0 + 8][ks + 2 * tg];
                al[mi][2] = *(const uint32_t*)&As[1][r0][ks + 2 * tg + 8];
                al[mi][3] = *(const uint32_t*)&As[1][r0 + 8][ks + 2 * tg + 8];
            }
#pragma unroll
            for (int nj = 0; nj < 4; nj++) {
                int n = wn * 32 + nj * 8 + g;
                uint32_t bh0 = *(const uint32_t*)&Bs[0][n][ks + 2 * tg];
                uint32_t bh1 = *(const uint32_t*)&Bs[0][n][ks + 2 * tg + 8];
                uint32_t bl0 = *(const uint32_t*)&Bs[1][n][ks + 2 * tg];
                uint32_t bl1 = *(const uint32_t*)&Bs[1][n][ks + 2 * tg + 8];
#pragma unroll
                for (int mi = 0; mi < 2; mi++) {
                    mma16816(acc[mi][nj], ah[mi], bh0, bh1);
                    mma16816(acc[mi][nj], ah[mi], bl0, bl1);
                    mma16816(acc[mi][nj], al[mi], bh0, bh1);
                }
            }
        }
        __syncthreads();
        if (kt + 1 < nk) {
            g_store(st, As, Bs, tid);
            __syncthreads();
        }
    }

#pragma unroll
    for (int mi = 0; mi < 2; mi++) {
#pragma unroll
        for (int nj = 0; nj < 4; nj++) {
            int r = bm0 + wm * 32 + mi * 16 + g;
            int nc = bn0 + wn * 32 + nj * 8 + 2 * tg;
            float b0 = bias[nc], b1 = bias[nc + 1];
            float2 v0 = make_float2(acc[mi][nj][0] + b0, acc[mi][nj][1] + b1);
            float2 v1 = make_float2(acc[mi][nj][2] + b0, acc[mi][nj][3] + b1);
            *(float2*)&C[(size_t)r * N + nc] = v0;
            *(float2*)&C[(size_t)(r + 8) * N + nc] = v1;
        }
    }
}

// ---------------- fp16 2-pass out-GEMM: 128x128 block, 32m x 64n warp tile ----------------
// A fp16 hi/lo [M][K], B single fp16 [N][K]. BK=32, cp.async double-buffered.
// Per stage (halfs): Ahi[128*40] Alo[128*40] B[128*40] = 15360 halfs (30720 B).
#define HS_STG 15360

extern __shared__ __half gh_smem[];

__global__ __launch_bounds__(256, 2) void gemm_half_kernel(
    const __half* __restrict__ Ahi, const __half* __restrict__ Alo,
    const __half* __restrict__ B, const float* __restrict__ bias, float* __restrict__ C, int M,
    int N, int K) {
    const int tid = threadIdx.x;
    const int lane = tid & 31, warp = tid >> 5;
    const int wm = warp & 3, wn = warp >> 2;  // 4m x 2n warps
    const int g = lane >> 2, tg = lane & 3;

    const int nt = N >> 7;
    int bid = blockIdx.x;
    int panel = bid / (4 * nt);
    int ii = bid - panel * 4 * nt;
    const int bm0 = (panel * 4 + (ii & 3)) << 7;
    const int bn0 = (ii >> 2) << 7;

    const uint32_t sbase = (uint32_t)__cvta_generic_to_shared(gh_smem);

    float acc[2][8][4];
#pragma unroll
    for (int mi = 0; mi < 2; mi++)
#pragma unroll
        for (int nj = 0; nj < 8; nj++)
#pragma unroll
            for (int e = 0; e < 4; e++) acc[mi][nj][e] = 0.f;

    auto fill = [&](int s, int k0) {
        uint32_t sb = sbase + s * HS_STG * 2;
#pragma unroll
        for (int q = 0; q < 2; q++) {
            int idx = q * 256 + tid;
            int r = idx >> 2, cg = idx & 3;
            uint32_t off = (r * 40 + cg * 8) * 2;
            cp16s(sb + off, Ahi + (size_t)(bm0 + r) * K + k0 + cg * 8);
            cp16s(sb + 5120 * 2 + off, Alo + (size_t)(bm0 + r) * K + k0 + cg * 8);
            cp16s(sb + 10240 * 2 + off, B + (size_t)(bn0 + r) * K + k0 + cg * 8);
        }
        asm volatile("cp.async.commit_group;");
    };

    fill(0, 0);
    fill(1, 32);
    const int nk = K / 32;

    for (int kt = 0; kt < nk; kt++) {
        asm volatile("cp.async.wait_group 1;");
        __syncthreads();
        const int s = kt & 1;
        const __half* pa = gh_smem + s * HS_STG;
        const __half* pl = pa + 5120;
        const __half* pb = pa + 10240;

#pragma unroll
        for (int ks = 0; ks < 32; ks += 16) {
            uint32_t ah[2][4], al[2][4];
#pragma unroll
            for (int mi = 0; mi < 2; mi++) {
                int r0 = wm * 32 + mi * 16 + g;
                ah[mi][0] = *(const uint32_t*)&pa[r0 * 40 + ks + 2 * tg];
                ah[mi][1] = *(const uint32_t*)&pa[(r0 + 8) * 40 + ks + 2 * tg];
                ah[mi][2] = *(const uint32_t*)&pa[r0 * 40 + ks + 2 * tg + 8];
                ah[mi][3] = *(const uint32_t*)&pa[(r0 + 8) * 40 + ks + 2 * tg + 8];
                al[mi][0] = *(const uint32_t*)&pl[r0 * 40 + ks + 2 * tg];
                al[mi][1] = *(const uint32_t*)&pl[(r0 + 8) * 40 + ks + 2 * tg];
                al[mi][2] = *(const uint32_t*)&pl[r0 * 40 + ks + 2 * tg + 8];
                al[mi][3] = *(const uint32_t*)&pl[(r0 + 8) * 40 + ks + 2 * tg + 8];
            }
#pragma unroll
            for (int nj = 0; nj < 8; nj++) {
                int n = wn * 64 + nj * 8 + g;
                uint32_t b0 = *(const uint32_t*)&pb[n * 40 + ks + 2 * tg];
                uint32_t b1 = *(const uint32_t*)&pb[n * 40 + ks + 2 * tg + 8];
#pragma unroll
                for (int mi = 0; mi < 2; mi++) {
                    mma16816h(acc[mi][nj], ah[mi], b0, b1);
                    mma16816h(acc[mi][nj], al[mi], b0, b1);
                }
            }
        }
        __syncthreads();
        if (kt + 2 < nk) fill(s, (kt + 2) * 32);
    }

#pragma unroll
    for (int mi = 0; mi < 2; mi++) {
#pragma unroll
        for (int nj = 0; nj < 8; nj++) {
            int r = bm0 + wm * 32 + mi * 16 + g;
            int nc = bn0 + wn * 64 + nj * 8 + 2 * tg;
            float b0 = bias[nc], b1 = bias[nc + 1];
            float2 v0 = make_float2(acc[mi][nj][0] + b0, acc[mi][nj][1] + b1);
            float2 v1 = make_float2(acc[mi][nj][2] + b0, acc[mi][nj][3] + b1);
            *(float2*)&C[(size_t)r * N + nc] = v0;
            *(float2*)&C[(size_t)(r + 8) * N + nc] = v1;
        }
    }
}

// ---------------- persistent LSTM recurrence: mma.sync h@U (R14 proven, unchanged) ----------------
#define RSM_U_U2 16384
#define RSM_PC_OFF (RSM_U_U2 * 8)
#define RSM_CS_OFF (RSM_PC_OFF + 8 * 16 * 32 * 4)
#define RSM_TOTAL (RSM_CS_OFF + 512)

extern __shared__ char recur_smem_raw[];

__global__ __launch_bounds__(256) void recur_kernel() {
    uint2* sU = (uint2*)recur_smem_raw;
    float* pC = (float*)(recur_smem_raw + RSM_PC_OFF);
    float* csm = (float*)(recur_smem_raw + RSM_CS_OFF);

    const int i = blockIdx.x;
    const int tid = threadIdx.x;
    const int w = tid >> 5;
    const int l = tid & 31;
    const int g = l >> 2, tg = l & 3;

    {
        const float4* src = (const float4*)(g_Ufrag + (size_t)i * RSM_U_U2);
        float4* dst = (float4*)sU;
#pragma unroll
        for (int q = 0; q < 32; q++) dst[tid + q * 256] = src[tid + q * 256];
    }
    if (tid < 128) csm[tid] = 0.f;
    __syncthreads();

    const int a_off = g * 1024 + 2 * tg;

    for (int t = 0; t < 256; t++) {
        float acc[4][4];
#pragma unroll
        for (int q = 0; q < 4; q++)
#pragma unroll
            for (int e = 0; e < 4; e++) acc[q][e] = 0.f;

        if (t > 0) {
            const int rp = (t - 1) & 1;
            const unsigned* Hhi = (const unsigned*)g_Hphi[rp];
            const unsigned* Hlo = (const unsigned*)g_Hplo[rp];
            uint32_t ahf[8][4], alf[8][4];
#pragma unroll
            for (int cc = 0; cc < 8; cc++) {
                int c = w * 8 + cc;
                int e0 = (a_off + 16 * c) >> 1;
                ahf[cc][0] = __ldcg(Hhi + e0);
                ahf[cc][1] = __ldcg(Hhi + e0 + 4096);
                ahf[cc][2] = __ldcg(Hhi + e0 + 4);
                ahf[cc][3] = __ldcg(Hhi + e0 + 4100);
                alf[cc][0] = __ldcg(Hlo + e0);
                alf[cc][1] = __ldcg(Hlo + e0 + 4096);
                alf[cc][2] = __ldcg(Hlo + e0 + 4);
                alf[cc][3] = __ldcg(Hlo + e0 + 4100);
            }
#pragma unroll
            for (int cc = 0; cc < 8; cc++) {
                int c = w * 8 + cc;
#pragma unroll
                for (int q = 0; q < 4; q++) {
                    uint2 bh = sU[(c * 4 + q) * 32 + l];
                    uint2 bl = sU[((64 + c) * 4 + q) * 32 + l];
                    mma16816(acc[q], ahf[cc], bh.x, bh.y);
                    mma16816(acc[q], ahf[cc], bl.x, bl.y);
                    mma16816(acc[q], alf[cc], bh.x, bh.y);
                }
            }
        }

        {
            float* base = pC + w * 512;
#pragma unroll
            for (int q = 0; q < 4; q++) {
                int n = 8 * q + 2 * tg;
                base[g * 32 + n] = acc[q][0];
                base[g * 32 + n + 1] = acc[q][1];
                base[(g + 8) * 32 + n] = acc[q][2];
                base[(g + 8) * 32 + n + 1] = acc[q][3];
            }
        }
        __syncthreads();

        if (tid < 128) {
            int b = tid >> 3, j = tid & 7;
            float s0 = 0.f, s1 = 0.f, s2 = 0.f, s3 = 0.f;
#pragma unroll
            for (int ww = 0; ww < 8; ww++) {
                const float* p = pC + ww * 512 + b * 32 + j;
                s0 += p[0];
                s1 += p[8];
                s2 += p[16];
                s3 += p[24];
            }
            int n = 8 * i + j;
            int row = b * 256 + t;
            const float* xg = g_XG + (size_t)row * 4096 + n;
            float pf = s0 + xg[0];
            float pi = s1 + xg[1024];
            float pc = s2 + xg[2048];
            float po = s3 + xg[3072];
            float f = 1.f / (1.f + expf(-pf));
            float ig = 1.f / (1.f + expf(-pi));
            float cd = tanhf(pc);
            float o = 1.f / (1.f + expf(-po));
            float c = f * csm[tid] + ig * cd;
            csm[tid] = c;
            float h = o * tanhf(c);
            bf16 hh = __float2bfloat16(h);
            bf16 hl2 = __float2bfloat16(h - __bfloat162float(hh));
            int wp = t & 1;
            g_Hphi[wp][b * 1024 + n] = hh;
            g_Hplo[wp][b * 1024 + n] = hl2;
            __half fh = __float2half(h);
            __half fl = __float2half(h - __half2float(fh));
            size_t hidx = (size_t)row * 1024 + n;
            g_HShi[hidx] = fh;
            g_HSlo[hidx] = fl;
        }

        if (t < 255) {
            __syncthreads();
            if (tid == 0) {
                unsigned* ctr = &g_ctr[t];
                asm volatile("red.release.gpu.global.add.u32 [%0], %1;" ::"l"(ctr), "r"(1u)
                             : "memory");
                unsigned v;
                do {
                    asm volatile("ld.acquire.gpu.global.u32 %0, [%1];" : "=r"(v) : "l"(ctr)
                                 : "memory");
                } while (v < (unsigned)NB);
            }
            __syncthreads();
        }
    }
}

// ---------------- launch ----------------
extern "C" void kernel_launch(void* const* d_in, const int* in_sizes, int n_in, void* d_out,
                              int out_size) {
    const int* tokens = (const int*)d_in[0];
    const float* emb = (const float*)d_in[1];
    const float* w_f = (const float*)d_in[2];
    const float* u_f = (const float*)d_in[3];
    const float* b_f = (const float*)d_in[4];
    const float* w_i = (const float*)d_in[5];
    const float* u_i = (const float*)d_in[6];
    const float* b_i = (const float*)d_in[7];
    const float* w_c = (const float*)d_in[8];
    const float* u_c = (const float*)d_in[9];
    const float* b_c = (const float*)d_in[10];
    const float* w_o = (const float*)d_in[11];
    const float* u_o = (const float*)d_in[12];
    const float* b_o = (const float*)d_in[13];
    const float* w_out = (const float*)d_in[14];
    const float* b_out = (const float*)d_in[15];
    float* out = (float*)d_out;

    cudaFuncSetAttribute(recur_kernel, cudaFuncAttributeMaxDynamicSharedMemorySize, RSM_TOTAL);
    cudaFuncSetAttribute(gemm_half_kernel, cudaFuncAttributeMaxDynamicSharedMemorySize,
                         2 * HS_STG * 2);

    void *p_xhi, *p_xlo, *p_wch, *p_wcl, *p_bcat, *p_xg, *p_hshi, *p_hslo, *p_woh;
    cudaGetSymbolAddress(&p_xhi, g_Xhi);
    cudaGetSymbolAddress(&p_xlo, g_Xlo);
    cudaGetSymbolAddress(&p_wch, g_WcatT_hi);
    cudaGetSymbolAddress(&p_wcl, g_WcatT_lo);
    cudaGetSymbolAddress(&p_bcat, g_bcat);
    cudaGetSymbolAddress(&p_xg, g_XG);
    cudaGetSymbolAddress(&p_hshi, g_HShi);
    cudaGetSymbolAddress(&p_hslo, g_HSlo);
    cudaGetSymbolAddress(&p_woh, g_WoutT_h);

    // idx 0: all prep (wout transpose, gather, wcat, ufrag, bcat, ctrs)
    prep_all_kernel<<<4096, 256>>>(tokens, emb, w_f, w_i, w_c, w_o, u_f, u_i, u_c, u_o, b_f,
                                   b_i, b_c, b_o, w_out);

    // idx 1: XG = X @ Wcat + bcat   (M=4096, N=4096, K=1024), bf16 3-pass
    gemm_split_kernel<<<dim3(4096 / 64, 4096 / 128), 256>>>(
        (const bf16*)p_xhi, (const bf16*)p_xlo, (const bf16*)p_wch, (const bf16*)p_wcl,
        (const float*)p_bcat, (float*)p_xg, R_, 4 * H_, H_);

    // idx 2: sequential LSTM recurrence
    recur_kernel<<<NB, 256, RSM_TOTAL>>>();

    // idx 3 (ncu-profiled slot): logits = HS @ w_out + b_out, fp16 2-pass, 128x128 tiles
    gemm_half_kernel<<<(R_ / 128) * (V_ / 128), 256, 2 * HS_STG * 2>>>(
        (const __half*)p_hshi, (const __half*)p_hslo, (const __half*)p_woh, b_out, out, R_, V_,
        H_);
}